// round 1
// baseline (speedup 1.0000x reference)
#include <cuda_runtime.h>
#include <cstddef>

#define EMBED 256
#define NQv   5440
#define NBATCH 4
#define M_TOTAL (NBATCH * NQv)   // 21760, divisible by 128

// Scratch (allocation-free rule: __device__ globals)
__device__ float g_values [(size_t)M_TOTAL * 256];
__device__ float g_off    [(size_t)M_TOTAL * 256];
__device__ float g_attn   [(size_t)M_TOTAL * 128];
__device__ float g_sampled[(size_t)M_TOTAL * 256];

// ---------------------------------------------------------------------------
// SGEMM with bias: C[M,N] = (A (+pos broadcast by q=row%NQ)) @ B[K=256,N] + bias
// Tiles: BM=128, BN=64, BK=16, 256 threads, 8x4 micro-tile per thread.
// ---------------------------------------------------------------------------
#define BM 128
#define BN 64
#define BK 16

__global__ __launch_bounds__(256) void sgemm_bias(
    const float* __restrict__ A, const float* __restrict__ pos,
    const float* __restrict__ B, const float* __restrict__ bias,
    float* __restrict__ C, int Ncols)
{
    __shared__ float As[BK][BM];
    __shared__ float Bs[BK][BN];

    const int tid  = threadIdx.x;
    const int row0 = blockIdx.x * BM;
    const int col0 = blockIdx.y * BN;
    const int tx   = tid & 15;   // 16 col-groups of 4
    const int ty   = tid >> 4;   // 16 row-groups of 8

    float acc[8][4];
#pragma unroll
    for (int i = 0; i < 8; i++)
#pragma unroll
        for (int j = 0; j < 4; j++) acc[i][j] = 0.f;

    for (int k0 = 0; k0 < 256; k0 += BK) {
        // Load A tile: 128 rows x 16 cols = 512 float4, 2 per thread
#pragma unroll
        for (int i = 0; i < 2; i++) {
            int f  = tid + i * 256;
            int r  = f >> 2;
            int c4 = (f & 3) * 4;
            int grow = row0 + r;
            float4 v = *(const float4*)&A[(size_t)grow * 256 + k0 + c4];
            if (pos) {
                int q = grow % NQv;
                float4 pv = *(const float4*)&pos[(size_t)q * 256 + k0 + c4];
                v.x += pv.x; v.y += pv.y; v.z += pv.z; v.w += pv.w;
            }
            As[c4 + 0][r] = v.x;
            As[c4 + 1][r] = v.y;
            As[c4 + 2][r] = v.z;
            As[c4 + 3][r] = v.w;
        }
        // Load B tile: 16 rows x 64 cols = 256 float4, 1 per thread
        {
            int r  = tid >> 4;
            int c4 = (tid & 15) * 4;
            *(float4*)&Bs[r][c4] =
                *(const float4*)&B[(size_t)(k0 + r) * Ncols + col0 + c4];
        }
        __syncthreads();

#pragma unroll
        for (int kk = 0; kk < BK; kk++) {
            float4 a0 = *(const float4*)&As[kk][ty * 8];
            float4 a1 = *(const float4*)&As[kk][ty * 8 + 4];
            float4 bv = *(const float4*)&Bs[kk][tx * 4];
            float a[8] = {a0.x, a0.y, a0.z, a0.w, a1.x, a1.y, a1.z, a1.w};
            float b[4] = {bv.x, bv.y, bv.z, bv.w};
#pragma unroll
            for (int i = 0; i < 8; i++)
#pragma unroll
                for (int j = 0; j < 4; j++)
                    acc[i][j] += a[i] * b[j];
        }
        __syncthreads();
    }

    float4 bv = *(const float4*)&bias[col0 + tx * 4];
#pragma unroll
    for (int i = 0; i < 8; i++) {
        int grow = row0 + ty * 8 + i;
        float4 o;
        o.x = acc[i][0] + bv.x;
        o.y = acc[i][1] + bv.y;
        o.z = acc[i][2] + bv.z;
        o.w = acc[i][3] + bv.w;
        *(float4*)&C[(size_t)grow * Ncols + col0 + tx * 4] = o;
    }
}

// ---------------------------------------------------------------------------
// Deformable sampling + per-head softmax + weighted sum.
// One block per (n, q). 8 warps = 8 heads, lane = dh (0..31).
// ---------------------------------------------------------------------------
__global__ __launch_bounds__(256) void deform_sample(
    const float* __restrict__ refp)
{
    const int b = blockIdx.x;       // 0 .. M_TOTAL-1
    const int n = b / NQv;
    const int q = b - n * NQv;

    __shared__ float s_off[256];
    __shared__ float s_attn[128];

    const int tid = threadIdx.x;
    s_off[tid] = g_off[(size_t)b * 256 + tid];
    if (tid < 128) s_attn[tid] = g_attn[(size_t)b * 128 + tid];
    __syncthreads();

    const float ref0 = refp[q * 2 + 0];
    const float ref1 = refp[q * 2 + 1];

    const int m    = tid >> 5;   // head
    const int lane = tid & 31;   // dh

    // Softmax over 16 logits for this head (head-major layout: m*16 + l*4+p)
    const float* la = &s_attn[m * 16];
    float mx = la[0];
#pragma unroll
    for (int k = 1; k < 16; k++) mx = fmaxf(mx, la[k]);
    float ssum = 0.f;
#pragma unroll
    for (int k = 0; k < 16; k++) ssum += __expf(la[k] - mx);
    const float inv = 1.f / ssum;

    const int   startT[4] = {0, 4096, 5120, 5376};
    const int   hwT[4]    = {64, 32, 16, 8};

    const float* vbase = g_values + (size_t)n * NQv * 256 + m * 32 + lane;

    float acc = 0.f;
#pragma unroll
    for (int k = 0; k < 16; k++) {
        const int l = k >> 2;
        const int p = k & 3;
        const float wk = __expf(la[k] - mx) * inv;

        // off layout is level-major: ((l*8 + m)*4 + p)*2 + c
        const int oidx = ((l * 8 + m) * 4 + p) * 2;
        // grid is flipped: x uses channel 1, y uses channel 0
        const float gy = ref0 + s_off[oidx + 0];
        const float gx = ref1 + s_off[oidx + 1];

        const int W = hwT[l];
        const int H = hwT[l];
        const int st = startT[l];

        const float x = (gx + 1.f) * (W * 0.5f) - 0.5f;
        const float y = (gy + 1.f) * (H * 0.5f) - 0.5f;
        const float x0f = floorf(x);
        const float y0f = floorf(y);
        const float wx = x - x0f;
        const float wy = y - y0f;
        const int x0 = (int)x0f;
        const int y0 = (int)y0f;

        float v[4];
#pragma unroll
        for (int c = 0; c < 4; c++) {
            const int yi = y0 + (c >> 1);
            const int xi = x0 + (c & 1);
            const bool valid = (xi >= 0) & (xi < W) & (yi >= 0) & (yi < H);
            const int yc = min(max(yi, 0), H - 1);
            const int xc = min(max(xi, 0), W - 1);
            float vv = __ldg(&vbase[(size_t)(st + yc * W + xc) * 256]);
            v[c] = valid ? vv : 0.f;
        }
        const float bil = (v[0] * (1.f - wx) + v[1] * wx) * (1.f - wy)
                        + (v[2] * (1.f - wx) + v[3] * wx) * wy;
        acc += wk * bil;
    }

    g_sampled[(size_t)b * 256 + tid] = acc;
}

// ---------------------------------------------------------------------------
extern "C" void kernel_launch(void* const* d_in, const int* in_sizes, int n_in,
                              void* d_out, int out_size)
{
    const float* hs     = (const float*)d_in[0];   // (4, 5440, 256)
    const float* pos    = (const float*)d_in[1];   // (5440, 256)
    const float* refp   = (const float*)d_in[2];   // (5440, 2)
    // d_in[3] = spatial_shapes (fixed, hardcoded)
    const float* W_off  = (const float*)d_in[4];
    const float* b_off  = (const float*)d_in[5];
    const float* W_attn = (const float*)d_in[6];
    const float* b_attn = (const float*)d_in[7];
    const float* W_val  = (const float*)d_in[8];
    const float* b_val  = (const float*)d_in[9];
    const float* W_out  = (const float*)d_in[10];
    const float* b_out  = (const float*)d_in[11];
    float* out = (float*)d_out;

    float *gv, *go, *ga, *gs;
    cudaGetSymbolAddress((void**)&gv, g_values);
    cudaGetSymbolAddress((void**)&go, g_off);
    cudaGetSymbolAddress((void**)&ga, g_attn);
    cudaGetSymbolAddress((void**)&gs, g_sampled);

    dim3 grid256(M_TOTAL / BM, 256 / BN);
    dim3 grid128(M_TOTAL / BM, 128 / BN);

    // values = hs @ W_val + b_val
    sgemm_bias<<<grid256, 256>>>(hs, nullptr, W_val, b_val, gv, 256);
    // off = (hs + pos) @ W_off + b_off
    sgemm_bias<<<grid256, 256>>>(hs, pos, W_off, b_off, go, 256);
    // attn = (hs + pos) @ W_attn + b_attn
    sgemm_bias<<<grid128, 256>>>(hs, pos, W_attn, b_attn, ga, 128);
    // sampling + softmax + weighted sum -> g_sampled
    deform_sample<<<M_TOTAL, 256>>>(refp);
    // out = g_sampled @ W_out + b_out
    sgemm_bias<<<grid256, 256>>>(gs, nullptr, W_out, b_out, out, 256);
}

// round 2
// speedup vs baseline: 1.2433x; 1.2433x over previous
#include <cuda_runtime.h>
#include <cstddef>

#define NQv    5440
#define NBATCH 4
#define M_TOTAL (NBATCH * NQv)   // 21760

// Scratch (allocation-free rule: __device__ globals)
__device__ float g_values [(size_t)M_TOTAL * 256];
__device__ float g_off    [(size_t)M_TOTAL * 256];
__device__ float g_attn   [(size_t)M_TOTAL * 128];
__device__ float g_sampled[(size_t)M_TOTAL * 256];

// ---------------------------------------------------------------------------
// SGEMM with bias: C[M,N] = (A (+pos broadcast by q=row%NQ)) @ B[K=256,N] + bias
// BM=128, BN=64, BK=8, 128 threads, 8x8 microtile per thread.
// Grid = 680 blocks -> fits in one resident wave on 148 SMs.
// ---------------------------------------------------------------------------
#define BM 128
#define BN 64
#define BK 8

__global__ __launch_bounds__(128) void sgemm_bias(
    const float* __restrict__ A, const float* __restrict__ pos,
    const float* __restrict__ B, const float* __restrict__ bias,
    float* __restrict__ C, int Ncols)
{
    __shared__ float As[BK][BM + 4];
    __shared__ float Bs[BK][BN];

    const int tid  = threadIdx.x;
    const int row0 = blockIdx.x * BM;
    const int col0 = blockIdx.y * BN;
    const int tx   = tid & 7;     // 8 col groups of 8
    const int ty   = tid >> 3;    // 16 row groups of 8

    // A loader: thread loads rows ar and ar+64, 4 floats at ac
    const int ar = tid >> 1;
    const int ac = (tid & 1) * 4;
    const int grow0 = row0 + ar;
    const int grow1 = grow0 + 64;
    const float* A0 = A + (size_t)grow0 * 256 + ac;
    const float* A1 = A + (size_t)grow1 * 256 + ac;
    const float* P0 = nullptr;
    const float* P1 = nullptr;
    if (pos) {
        P0 = pos + (size_t)(grow0 % NQv) * 256 + ac;
        P1 = pos + (size_t)(grow1 % NQv) * 256 + ac;
    }
    // B loader: row br (0..7), 4 floats at bc
    const int br = tid >> 4;
    const int bc = (tid & 15) * 4;
    const float* B0 = B + (size_t)br * Ncols + col0 + bc;

    float acc[8][8];
#pragma unroll
    for (int i = 0; i < 8; i++)
#pragma unroll
        for (int j = 0; j < 8; j++) acc[i][j] = 0.f;

    for (int k0 = 0; k0 < 256; k0 += BK) {
        float4 a0 = *(const float4*)(A0 + k0);
        float4 a1 = *(const float4*)(A1 + k0);
        if (pos) {
            float4 p0 = *(const float4*)(P0 + k0);
            float4 p1 = *(const float4*)(P1 + k0);
            a0.x += p0.x; a0.y += p0.y; a0.z += p0.z; a0.w += p0.w;
            a1.x += p1.x; a1.y += p1.y; a1.z += p1.z; a1.w += p1.w;
        }
        As[ac + 0][ar] = a0.x;  As[ac + 1][ar] = a0.y;
        As[ac + 2][ar] = a0.z;  As[ac + 3][ar] = a0.w;
        As[ac + 0][ar + 64] = a1.x;  As[ac + 1][ar + 64] = a1.y;
        As[ac + 2][ar + 64] = a1.z;  As[ac + 3][ar + 64] = a1.w;

        *(float4*)&Bs[br][bc] = *(const float4*)(B0 + (size_t)k0 * Ncols);
        __syncthreads();

#pragma unroll
        for (int kk = 0; kk < BK; kk++) {
            float4 x0 = *(const float4*)&As[kk][ty * 8];
            float4 x1 = *(const float4*)&As[kk][ty * 8 + 4];
            float4 y0 = *(const float4*)&Bs[kk][tx * 8];
            float4 y1 = *(const float4*)&Bs[kk][tx * 8 + 4];
            float av[8] = {x0.x, x0.y, x0.z, x0.w, x1.x, x1.y, x1.z, x1.w};
            float bv[8] = {y0.x, y0.y, y0.z, y0.w, y1.x, y1.y, y1.z, y1.w};
#pragma unroll
            for (int i = 0; i < 8; i++)
#pragma unroll
                for (int j = 0; j < 8; j++)
                    acc[i][j] += av[i] * bv[j];
        }
        __syncthreads();
    }

    float4 bb0 = *(const float4*)&bias[col0 + tx * 8];
    float4 bb1 = *(const float4*)&bias[col0 + tx * 8 + 4];
    const float bvr[8] = {bb0.x, bb0.y, bb0.z, bb0.w, bb1.x, bb1.y, bb1.z, bb1.w};
#pragma unroll
    for (int i = 0; i < 8; i++) {
        float* Cr = C + (size_t)(row0 + ty * 8 + i) * Ncols + col0 + tx * 8;
        float4 o0, o1;
        o0.x = acc[i][0] + bvr[0]; o0.y = acc[i][1] + bvr[1];
        o0.z = acc[i][2] + bvr[2]; o0.w = acc[i][3] + bvr[3];
        o1.x = acc[i][4] + bvr[4]; o1.y = acc[i][5] + bvr[5];
        o1.z = acc[i][6] + bvr[6]; o1.w = acc[i][7] + bvr[7];
        *(float4*)Cr       = o0;
        *(float4*)(Cr + 4) = o1;
    }
}

// ---------------------------------------------------------------------------
// Deformable sampling + per-head softmax + weighted sum.
// One block per (n, q). 8 warps = 8 heads, lane = dh (0..31).
// Lanes 0..15 compute per-point prep (softmax weight folded into 4 combined
// corner weights + 4 pre-scaled indices) -> shared; then all 32 lanes run a
// tight gather loop: 2x LDS.128 (broadcast) + 4 LDG + 4 FFMA per point.
// ---------------------------------------------------------------------------
__global__ __launch_bounds__(256) void deform_sample(
    const float* __restrict__ refp)
{
    const int b = blockIdx.x;       // 0 .. M_TOTAL-1
    const int n = b / NQv;
    const int q = b - n * NQv;

    __shared__ float  s_off[256];
    __shared__ float  s_attn[128];
    __shared__ int4   s_idx[8][16];
    __shared__ float4 s_w[8][16];

    const int tid = threadIdx.x;
    s_off[tid] = g_off[(size_t)b * 256 + tid];
    if (tid < 128) s_attn[tid] = g_attn[(size_t)b * 128 + tid];
    __syncthreads();

    const int m    = tid >> 5;   // head
    const int lane = tid & 31;
    const int k    = lane & 15;  // point id (lanes 16-31 mirror 0-15)

    // --- lane-parallel softmax over the head's 16 logits ---
    float logit = s_attn[m * 16 + k];
    float mx = logit;
#pragma unroll
    for (int s = 8; s > 0; s >>= 1)
        mx = fmaxf(mx, __shfl_xor_sync(0xffffffffu, mx, s));
    float e = __expf(logit - mx);
    float ssum = e;
#pragma unroll
    for (int s = 8; s > 0; s >>= 1)
        ssum += __shfl_xor_sync(0xffffffffu, ssum, s);
    const float wk = e / ssum;

    if (lane < 16) {
        const int l = k >> 2;
        const int p = k & 3;
        const float ref0 = refp[q * 2 + 0];
        const float ref1 = refp[q * 2 + 1];

        // off layout is level-major: ((l*8 + m)*4 + p)*2 + c ; grid is flipped
        const int oidx = ((l * 8 + m) * 4 + p) * 2;
        const float gy = ref0 + s_off[oidx + 0];
        const float gx = ref1 + s_off[oidx + 1];

        const int hw = 64 >> l;                      // 64,32,16,8
        const int st = (16384 - (16384 >> (2 * l))) / 3;  // 0,4096,5120,5376

        const float scale = hw * 0.5f;
        const float x = gx * scale + (scale - 0.5f);
        const float y = gy * scale + (scale - 0.5f);
        const float x0f = floorf(x);
        const float y0f = floorf(y);
        const float wx = x - x0f;
        const float wy = y - y0f;
        const int x0 = (int)x0f;
        const int y0 = (int)y0f;
        const int x1 = x0 + 1;
        const int y1 = y0 + 1;

        const bool vx0 = (x0 >= 0) & (x0 < hw);
        const bool vx1 = (x1 >= 0) & (x1 < hw);
        const bool vy0 = (y0 >= 0) & (y0 < hw);
        const bool vy1 = (y1 >= 0) & (y1 < hw);

        const int xc0 = min(max(x0, 0), hw - 1);
        const int xc1 = min(max(x1, 0), hw - 1);
        const int yc0 = min(max(y0, 0), hw - 1);
        const int yc1 = min(max(y1, 0), hw - 1);

        int4 idx;
        idx.x = (st + yc0 * hw + xc0) * 256;
        idx.y = (st + yc0 * hw + xc1) * 256;
        idx.z = (st + yc1 * hw + xc0) * 256;
        idx.w = (st + yc1 * hw + xc1) * 256;

        float4 w;
        w.x = wk * (1.f - wx) * (1.f - wy) * (float)(vx0 & vy0);
        w.y = wk * wx * (1.f - wy)         * (float)(vx1 & vy0);
        w.z = wk * (1.f - wx) * wy         * (float)(vx0 & vy1);
        w.w = wk * wx * wy                 * (float)(vx1 & vy1);

        s_idx[m][k] = idx;
        s_w[m][k]   = w;
    }
    __syncwarp();

    // --- gather + weighted sum: all 32 lanes, lane = dh channel ---
    const float* __restrict__ vb =
        g_values + (size_t)n * ((size_t)NQv * 256) + m * 32 + lane;

    float acc = 0.f;
#pragma unroll
    for (int kk = 0; kk < 16; kk++) {
        const int4   id = s_idx[m][kk];
        const float4 w  = s_w[m][kk];
        acc += w.x * __ldg(vb + id.x);
        acc += w.y * __ldg(vb + id.y);
        acc += w.z * __ldg(vb + id.z);
        acc += w.w * __ldg(vb + id.w);
    }

    g_sampled[(size_t)b * 256 + tid] = acc;
}

// ---------------------------------------------------------------------------
extern "C" void kernel_launch(void* const* d_in, const int* in_sizes, int n_in,
                              void* d_out, int out_size)
{
    const float* hs     = (const float*)d_in[0];   // (4, 5440, 256)
    const float* pos    = (const float*)d_in[1];   // (5440, 256)
    const float* refp   = (const float*)d_in[2];   // (5440, 2)
    // d_in[3] = spatial_shapes (fixed, hardcoded)
    const float* W_off  = (const float*)d_in[4];
    const float* b_off  = (const float*)d_in[5];
    const float* W_attn = (const float*)d_in[6];
    const float* b_attn = (const float*)d_in[7];
    const float* W_val  = (const float*)d_in[8];
    const float* b_val  = (const float*)d_in[9];
    const float* W_out  = (const float*)d_in[10];
    const float* b_out  = (const float*)d_in[11];
    float* out = (float*)d_out;

    float *gv, *go, *ga, *gs;
    cudaGetSymbolAddress((void**)&gv, g_values);
    cudaGetSymbolAddress((void**)&go, g_off);
    cudaGetSymbolAddress((void**)&ga, g_attn);
    cudaGetSymbolAddress((void**)&gs, g_sampled);

    dim3 grid256(M_TOTAL / BM, 256 / BN);
    dim3 grid128(M_TOTAL / BM, 128 / BN);

    // values = hs @ W_val + b_val
    sgemm_bias<<<grid256, 128>>>(hs, nullptr, W_val, b_val, gv, 256);
    // off = (hs + pos) @ W_off + b_off
    sgemm_bias<<<grid256, 128>>>(hs, pos, W_off, b_off, go, 256);
    // attn = (hs + pos) @ W_attn + b_attn
    sgemm_bias<<<grid128, 128>>>(hs, pos, W_attn, b_attn, ga, 128);
    // sampling + softmax + weighted sum -> g_sampled
    deform_sample<<<M_TOTAL, 256>>>(refp);
    // out = g_sampled @ W_out + b_out
    sgemm_bias<<<grid256, 128>>>(gs, nullptr, W_out, b_out, out, 256);
}

// round 4
// speedup vs baseline: 1.5775x; 1.2688x over previous
#include <cuda_runtime.h>
#include <cstddef>
#include <cstdint>

#define NQv    5440
#define NBATCH 4
#define M_TOTAL (NBATCH * NQv)   // 21760

// Scratch (allocation-free rule: __device__ globals)
__device__ float g_values [(size_t)M_TOTAL * 256];
__device__ float g_off    [(size_t)M_TOTAL * 256];
__device__ float g_attn   [(size_t)M_TOTAL * 128];
__device__ float g_sampled[(size_t)M_TOTAL * 256];

// ---------------------------------------------------------------------------
// 3xTF32 tensor-core GEMM with bias (fp32-accurate):
//   C[M,Ncols] = (A (+pos broadcast by q=row%NQ)) @ B[256,Ncols] + bias
// Split each operand x = hi + lo (hi = tf32(x), lo = tf32(x - hi)); accumulate
// A_hi*B_hi + A_hi*B_lo + A_lo*B_hi. Error ~fp32 (lo*lo dropped, ~2^-22).
// Block tile 128x64, BK=8, 256 threads (8 warps), warp tile 32x32,
// double-buffered smem, mma.sync.m16n8k8.tf32.
// ---------------------------------------------------------------------------
#define BM 128
#define BN 64
#define BK 8
#define ASTRIDE 12   // r*12 mod 32 + t4 covers all 32 banks -> conflict-free
#define BSTRIDE 72   // t4*72 mod 32 = t4*8 -> conflict-free

__device__ __forceinline__ uint32_t f2tf32(float x) {
    uint32_t r;
    asm("cvt.rna.tf32.f32 %0, %1;" : "=r"(r) : "f"(x));
    return r;
}

__device__ __forceinline__ void mma_tf32(float d[4],
    uint32_t a0, uint32_t a1, uint32_t a2, uint32_t a3,
    uint32_t b0, uint32_t b1)
{
    asm volatile(
        "mma.sync.aligned.m16n8k8.row.col.f32.tf32.tf32.f32 "
        "{%0,%1,%2,%3}, {%4,%5,%6,%7}, {%8,%9}, {%0,%1,%2,%3};\n"
        : "+f"(d[0]), "+f"(d[1]), "+f"(d[2]), "+f"(d[3])
        : "r"(a0), "r"(a1), "r"(a2), "r"(a3), "r"(b0), "r"(b1));
}

__device__ __forceinline__ void split_tf32(float x, uint32_t& hi, uint32_t& lo) {
    hi = f2tf32(x);
    lo = f2tf32(x - __uint_as_float(hi));
}

__global__ __launch_bounds__(256) void gemm_tf32x3(
    const float* __restrict__ A, const float* __restrict__ pos,
    const float* __restrict__ B, const float* __restrict__ bias,
    float* __restrict__ C, int Ncols)
{
    __shared__ uint32_t As[2][2][BM * ASTRIDE];   // [stage][hi/lo]
    __shared__ uint32_t Bs[2][2][BK * BSTRIDE];

    const int tid    = threadIdx.x;
    const int lane   = tid & 31;
    const int wid    = tid >> 5;
    const int warp_m = (wid & 3) * 32;     // 4 warps down M
    const int warp_n = (wid >> 2) * 32;    // 2 warps across N
    const int g      = lane >> 2;          // groupID 0..7
    const int t4     = lane & 3;           // threadInGroup 0..3

    const int row0 = blockIdx.x * BM;
    const int col0 = blockIdx.y * BN;

    // A loader: one float4 per thread per stage (128 rows x 8 k)
    const int ar  = tid >> 1;
    const int ac4 = (tid & 1) * 4;
    const float* A0 = A + (size_t)(row0 + ar) * 256 + ac4;
    const float* P0 = nullptr;
    if (pos) P0 = pos + (size_t)((row0 + ar) % NQv) * 256 + ac4;

    // B loader: one float2 per thread per stage (8 rows x 64 cols)
    const int br  = tid >> 5;
    const int bc2 = (tid & 31) * 2;
    const float* B0 = B + (size_t)br * Ncols + col0 + bc2;

    float acc[2][4][4];
#pragma unroll
    for (int mi = 0; mi < 2; mi++)
#pragma unroll
        for (int ni = 0; ni < 4; ni++)
#pragma unroll
            for (int j = 0; j < 4; j++) acc[mi][ni][j] = 0.f;

    float4 pa; float2 pb;

    auto fetch = [&](int k0) {
        pa = *(const float4*)(A0 + k0);
        if (pos) {
            float4 p = *(const float4*)(P0 + k0);
            pa.x += p.x; pa.y += p.y; pa.z += p.z; pa.w += p.w;
        }
        pb = *(const float2*)(B0 + (size_t)k0 * Ncols);
    };
    auto store = [&](int s) {
        uint4 ah, al;
        split_tf32(pa.x, ah.x, al.x);
        split_tf32(pa.y, ah.y, al.y);
        split_tf32(pa.z, ah.z, al.z);
        split_tf32(pa.w, ah.w, al.w);
        *(uint4*)&As[s][0][ar * ASTRIDE + ac4] = ah;
        *(uint4*)&As[s][1][ar * ASTRIDE + ac4] = al;
        uint2 bh, bl;
        split_tf32(pb.x, bh.x, bl.x);
        split_tf32(pb.y, bh.y, bl.y);
        *(uint2*)&Bs[s][0][br * BSTRIDE + bc2] = bh;
        *(uint2*)&Bs[s][1][br * BSTRIDE + bc2] = bl;
    };

    fetch(0);
    store(0);
    __syncthreads();

    int s = 0;
    for (int k0 = 0; k0 < 256; k0 += BK) {
        const bool more = (k0 + BK) < 256;
        if (more) fetch(k0 + BK);

        const uint32_t* ah = As[s][0];
        const uint32_t* al = As[s][1];
        const uint32_t* bh = Bs[s][0];
        const uint32_t* bl = Bs[s][1];

        uint32_t afh[2][4], afl[2][4];
#pragma unroll
        for (int mi = 0; mi < 2; mi++) {
            const int r = warp_m + mi * 16 + g;
            afh[mi][0] = ah[r * ASTRIDE + t4];
            afh[mi][1] = ah[(r + 8) * ASTRIDE + t4];
            afh[mi][2] = ah[r * ASTRIDE + t4 + 4];
            afh[mi][3] = ah[(r + 8) * ASTRIDE + t4 + 4];
            afl[mi][0] = al[r * ASTRIDE + t4];
            afl[mi][1] = al[(r + 8) * ASTRIDE + t4];
            afl[mi][2] = al[r * ASTRIDE + t4 + 4];
            afl[mi][3] = al[(r + 8) * ASTRIDE + t4 + 4];
        }
        uint32_t bfh[4][2], bfl[4][2];
#pragma unroll
        for (int ni = 0; ni < 4; ni++) {
            const int c = warp_n + ni * 8 + g;
            bfh[ni][0] = bh[t4 * BSTRIDE + c];
            bfh[ni][1] = bh[(t4 + 4) * BSTRIDE + c];
            bfl[ni][0] = bl[t4 * BSTRIDE + c];
            bfl[ni][1] = bl[(t4 + 4) * BSTRIDE + c];
        }
#pragma unroll
        for (int mi = 0; mi < 2; mi++)
#pragma unroll
            for (int ni = 0; ni < 4; ni++) {
                mma_tf32(acc[mi][ni], afh[mi][0], afh[mi][1], afh[mi][2], afh[mi][3],
                         bfh[ni][0], bfh[ni][1]);
                mma_tf32(acc[mi][ni], afh[mi][0], afh[mi][1], afh[mi][2], afh[mi][3],
                         bfl[ni][0], bfl[ni][1]);
                mma_tf32(acc[mi][ni], afl[mi][0], afl[mi][1], afl[mi][2], afl[mi][3],
                         bfh[ni][0], bfh[ni][1]);
            }

        if (more) {
            store(s ^ 1);
            __syncthreads();
            s ^= 1;
        }
    }

    // Epilogue: bias + store (c0,c1) at row, (c2,c3) at row+8
#pragma unroll
    for (int mi = 0; mi < 2; mi++) {
        const int r = row0 + warp_m + mi * 16 + g;
#pragma unroll
        for (int ni = 0; ni < 4; ni++) {
            const int c = col0 + warp_n + ni * 8 + t4 * 2;
            const float2 bb = *(const float2*)&bias[c];
            float2 o0, o1;
            o0.x = acc[mi][ni][0] + bb.x;
            o0.y = acc[mi][ni][1] + bb.y;
            o1.x = acc[mi][ni][2] + bb.x;
            o1.y = acc[mi][ni][3] + bb.y;
            *(float2*)&C[(size_t)r * Ncols + c]       = o0;
            *(float2*)&C[(size_t)(r + 8) * Ncols + c] = o1;
        }
    }
}

// ---------------------------------------------------------------------------
// Deformable sampling + per-head softmax + weighted sum.
// One block per (n, q). 8 warps = 8 heads.
// Prep (lanes 0..15): one point each -> 4 clamped indices + 4 combined weights.
// Gather: corner = lane/8, 4 channels per lane -> one LDG.128 covers all 4
// corners of a point across the warp. Cross-corner reduce via shfl.
// ---------------------------------------------------------------------------
__global__ __launch_bounds__(256) void deform_sample(
    const float* __restrict__ refp)
{
    const int b = blockIdx.x;       // 0 .. M_TOTAL-1
    const int n = b / NQv;
    const int q = b - n * NQv;

    __shared__ float s_off[256];
    __shared__ float s_attn[128];
    __shared__ int   s_idx[8][16][4];
    __shared__ float s_w[8][16][4];

    const int tid = threadIdx.x;
    s_off[tid] = g_off[(size_t)b * 256 + tid];
    if (tid < 128) s_attn[tid] = g_attn[(size_t)b * 128 + tid];
    __syncthreads();

    const int m    = tid >> 5;   // head
    const int lane = tid & 31;
    const int k    = lane & 15;  // point id (lanes 16-31 mirror 0-15)

    // --- lane-parallel softmax over the head's 16 logits ---
    float logit = s_attn[m * 16 + k];
    float mx = logit;
#pragma unroll
    for (int s = 8; s > 0; s >>= 1)
        mx = fmaxf(mx, __shfl_xor_sync(0xffffffffu, mx, s));
    float e = __expf(logit - mx);
    float ssum = e;
#pragma unroll
    for (int s = 8; s > 0; s >>= 1)
        ssum += __shfl_xor_sync(0xffffffffu, ssum, s);
    const float wk = e / ssum;

    if (lane < 16) {
        const int l = k >> 2;
        const int p = k & 3;
        const float ref0 = refp[q * 2 + 0];
        const float ref1 = refp[q * 2 + 1];

        // off layout is level-major: ((l*8 + m)*4 + p)*2 + c ; grid is flipped
        const int oidx = ((l * 8 + m) * 4 + p) * 2;
        const float gy = ref0 + s_off[oidx + 0];
        const float gx = ref1 + s_off[oidx + 1];

        const int hw = 64 >> l;                           // 64,32,16,8
        const int st = (16384 - (16384 >> (2 * l))) / 3;  // 0,4096,5120,5376

        const float scale = hw * 0.5f;
        const float x = gx * scale + (scale - 0.5f);
        const float y = gy * scale + (scale - 0.5f);
        const float x0f = floorf(x);
        const float y0f = floorf(y);
        const float wx = x - x0f;
        const float wy = y - y0f;
        const int x0 = (int)x0f;
        const int y0 = (int)y0f;
        const int x1 = x0 + 1;
        const int y1 = y0 + 1;

        const bool vx0 = (x0 >= 0) & (x0 < hw);
        const bool vx1 = (x1 >= 0) & (x1 < hw);
        const bool vy0 = (y0 >= 0) & (y0 < hw);
        const bool vy1 = (y1 >= 0) & (y1 < hw);

        const int xc0 = min(max(x0, 0), hw - 1);
        const int xc1 = min(max(x1, 0), hw - 1);
        const int yc0 = min(max(y0, 0), hw - 1);
        const int yc1 = min(max(y1, 0), hw - 1);

        int4 idx;
        idx.x = (st + yc0 * hw + xc0) * 256;
        idx.y = (st + yc0 * hw + xc1) * 256;
        idx.z = (st + yc1 * hw + xc0) * 256;
        idx.w = (st + yc1 * hw + xc1) * 256;

        float4 w;
        w.x = wk * (1.f - wx) * (1.f - wy) * (float)(vx0 & vy0);
        w.y = wk * wx * (1.f - wy)         * (float)(vx1 & vy0);
        w.z = wk * (1.f - wx) * wy         * (float)(vx0 & vy1);
        w.w = wk * wx * wy                 * (float)(vx1 & vy1);

        *(int4*)  &s_idx[m][k][0] = idx;
        *(float4*)&s_w[m][k][0]   = w;
    }
    __syncwarp();

    // --- gather: corner = lane/8, channels ch4*4..ch4*4+3 ---
    const int corner = lane >> 3;
    const int ch4    = lane & 7;
    const float* __restrict__ vb =
        g_values + (size_t)n * ((size_t)NQv * 256) + m * 32 + ch4 * 4;

    float4 acc = {0.f, 0.f, 0.f, 0.f};
#pragma unroll
    for (int kk = 0; kk < 16; kk++) {
        const int   id = s_idx[m][kk][corner];
        const float w  = s_w[m][kk][corner];
        const float4 v = *(const float4*)(vb + id);
        acc.x += w * v.x;
        acc.y += w * v.y;
        acc.z += w * v.z;
        acc.w += w * v.w;
    }

    // reduce across corners (lanes differing in bits 3,4)
#pragma unroll
    for (int s = 8; s <= 16; s <<= 1) {
        acc.x += __shfl_xor_sync(0xffffffffu, acc.x, s);
        acc.y += __shfl_xor_sync(0xffffffffu, acc.y, s);
        acc.z += __shfl_xor_sync(0xffffffffu, acc.z, s);
        acc.w += __shfl_xor_sync(0xffffffffu, acc.w, s);
    }

    if (lane < 8)
        *(float4*)&g_sampled[(size_t)b * 256 + m * 32 + lane * 4] = acc;
}

// ---------------------------------------------------------------------------
extern "C" void kernel_launch(void* const* d_in, const int* in_sizes, int n_in,
                              void* d_out, int out_size)
{
    const float* hs     = (const float*)d_in[0];   // (4, 5440, 256)
    const float* pos    = (const float*)d_in[1];   // (5440, 256)
    const float* refp   = (const float*)d_in[2];   // (5440, 2)
    // d_in[3] = spatial_shapes (fixed, hardcoded)
    const float* W_off  = (const float*)d_in[4];
    const float* b_off  = (const float*)d_in[5];
    const float* W_attn = (const float*)d_in[6];
    const float* b_attn = (const float*)d_in[7];
    const float* W_val  = (const float*)d_in[8];
    const float* b_val  = (const float*)d_in[9];
    const float* W_out  = (const float*)d_in[10];
    const float* b_out  = (const float*)d_in[11];
    float* out = (float*)d_out;

    float *gv, *go, *ga, *gs;
    cudaGetSymbolAddress((void**)&gv, g_values);
    cudaGetSymbolAddress((void**)&go, g_off);
    cudaGetSymbolAddress((void**)&ga, g_attn);
    cudaGetSymbolAddress((void**)&gs, g_sampled);

    dim3 grid256(M_TOTAL / BM, 256 / BN);
    dim3 grid128(M_TOTAL / BM, 128 / BN);

    // values = hs @ W_val + b_val
    gemm_tf32x3<<<grid256, 256>>>(hs, nullptr, W_val, b_val, gv, 256);
    // off = (hs + pos) @ W_off + b_off
    gemm_tf32x3<<<grid256, 256>>>(hs, pos, W_off, b_off, go, 256);
    // attn = (hs + pos) @ W_attn + b_attn
    gemm_tf32x3<<<grid128, 256>>>(hs, pos, W_attn, b_attn, ga, 128);
    // sampling + softmax + weighted sum -> g_sampled
    deform_sample<<<M_TOTAL, 256>>>(refp);
    // out = g_sampled @ W_out + b_out
    gemm_tf32x3<<<grid256, 256>>>(gs, nullptr, W_out, b_out, out, 256);
}

// round 5
// speedup vs baseline: 1.6667x; 1.0565x over previous
#include <cuda_runtime.h>
#include <cstddef>
#include <cstdint>

#define NQv    5440
#define NBATCH 4
#define M_TOTAL (NBATCH * NQv)   // 21760

// Scratch (allocation-free rule: __device__ globals)
__device__ float g_hpos   [(size_t)M_TOTAL * 256];
__device__ float g_values [(size_t)M_TOTAL * 256];
__device__ float g_off    [(size_t)M_TOTAL * 256];
__device__ float g_attn   [(size_t)M_TOTAL * 128];
__device__ float g_sampled[(size_t)M_TOTAL * 256];

// ---------------------------------------------------------------------------
// hs + pos (pos broadcast across batch)
// ---------------------------------------------------------------------------
__global__ __launch_bounds__(256) void add_pos(
    const float* __restrict__ hs, const float* __restrict__ pos,
    float* __restrict__ out)
{
    const int i = blockIdx.x * 256 + threadIdx.x;   // float4 index
    const int PQ = NQv * 64;                        // float4s per batch
    float4 a = ((const float4*)hs)[i];
    float4 p = ((const float4*)pos)[i % PQ];
    a.x += p.x; a.y += p.y; a.z += p.z; a.w += p.w;
    ((float4*)out)[i] = a;
}

// ---------------------------------------------------------------------------
// 3xTF32 tensor-core GEMM, cp.async staged, split-on-read:
//   C[M,Ncols] = A[M,256] @ B[256,Ncols] + bias
// Block 128x128, BK=8, 128 threads (4 warps), warp tile 64x64 (m16n8k8 x 4x8).
// 3-stage cp.async ring of RAW fp32 tiles; hi/lo tf32 split done in registers
// after fragment LDS (halves LDS traffic and smem vs storing hi/lo).
// ---------------------------------------------------------------------------
#define BM 128
#define BN 128
#define BK 8
#define AST 12    // A smem row stride: (g*12+t4) mod 32 all-distinct -> conflict-free
#define BST 136   // B smem row stride: (t4*8+g) mod 32 all-distinct -> conflict-free
#define STAGES 3

__device__ __forceinline__ uint32_t f2tf32(float x) {
    uint32_t r;
    asm("cvt.rna.tf32.f32 %0, %1;" : "=r"(r) : "f"(x));
    return r;
}
__device__ __forceinline__ void split_tf32(float x, uint32_t& hi, uint32_t& lo) {
    hi = f2tf32(x);
    lo = f2tf32(x - __uint_as_float(hi));
}
__device__ __forceinline__ void mma_tf32(float d[4],
    uint32_t a0, uint32_t a1, uint32_t a2, uint32_t a3,
    uint32_t b0, uint32_t b1)
{
    asm volatile(
        "mma.sync.aligned.m16n8k8.row.col.f32.tf32.tf32.f32 "
        "{%0,%1,%2,%3}, {%4,%5,%6,%7}, {%8,%9}, {%0,%1,%2,%3};\n"
        : "+f"(d[0]), "+f"(d[1]), "+f"(d[2]), "+f"(d[3])
        : "r"(a0), "r"(a1), "r"(a2), "r"(a3), "r"(b0), "r"(b1));
}
__device__ __forceinline__ void cp_async16(uint32_t saddr, const void* g) {
    asm volatile("cp.async.cg.shared.global [%0], [%1], 16;\n"
                 :: "r"(saddr), "l"(g));
}
__device__ __forceinline__ void cp_commit() {
    asm volatile("cp.async.commit_group;\n");
}
template <int N>
__device__ __forceinline__ void cp_wait() {
    asm volatile("cp.async.wait_group %0;\n" :: "n"(N));
}

__global__ __launch_bounds__(128, 2) void gemm_tf32x3(
    const float* __restrict__ A, const float* __restrict__ B,
    const float* __restrict__ bias, float* __restrict__ C, int Ncols)
{
    __shared__ float As[STAGES][BM * AST];
    __shared__ float Bs[STAGES][BK * BST];

    const int tid    = threadIdx.x;
    const int lane   = tid & 31;
    const int wid    = tid >> 5;
    const int warp_m = (wid & 1) * 64;
    const int warp_n = (wid >> 1) * 64;
    const int g      = lane >> 2;
    const int t4     = lane & 3;

    const int row0 = blockIdx.x * BM;
    const int col0 = blockIdx.y * BN;

    // copy assignments
    const int ar  = tid;               // A row (0..127)
    const int brr = tid >> 4;          // B k-row (0..7)
    const int bcc = (tid & 15) * 8;    // B col offset (0..120)
    const float* Ag = A + (size_t)(row0 + ar) * 256;
    const float* Bg = B + (size_t)brr * Ncols + col0 + bcc;

    uint32_t sA[STAGES], sB[STAGES];
#pragma unroll
    for (int s = 0; s < STAGES; s++) {
        sA[s] = (uint32_t)__cvta_generic_to_shared(&As[s][ar * AST]);
        sB[s] = (uint32_t)__cvta_generic_to_shared(&Bs[s][brr * BST + bcc]);
    }

    auto issue = [&](int s, int k0) {
        cp_async16(sA[s],      Ag + k0);
        cp_async16(sA[s] + 16, Ag + k0 + 4);
        const float* bg = Bg + (size_t)k0 * Ncols;
        cp_async16(sB[s],      bg);
        cp_async16(sB[s] + 16, bg + 4);
    };

    float acc[4][8][4];
#pragma unroll
    for (int mi = 0; mi < 4; mi++)
#pragma unroll
        for (int ni = 0; ni < 8; ni++)
#pragma unroll
            for (int j = 0; j < 4; j++) acc[mi][ni][j] = 0.f;

    issue(0, 0);  cp_commit();
    issue(1, 8);  cp_commit();

    for (int i = 0; i < 32; i++) {
        cp_wait<1>();
        __syncthreads();
        const int st = i % STAGES;
        const float* as_ = As[st];
        const float* bs_ = Bs[st];

        // fragment loads (raw fp32)
        float arf[4][4];
#pragma unroll
        for (int mi = 0; mi < 4; mi++) {
            const int r = warp_m + mi * 16 + g;
            arf[mi][0] = as_[r * AST + t4];
            arf[mi][1] = as_[(r + 8) * AST + t4];
            arf[mi][2] = as_[r * AST + t4 + 4];
            arf[mi][3] = as_[(r + 8) * AST + t4 + 4];
        }
        float brf[8][2];
#pragma unroll
        for (int ni = 0; ni < 8; ni++) {
            const int c = warp_n + ni * 8 + g;
            brf[ni][0] = bs_[t4 * BST + c];
            brf[ni][1] = bs_[(t4 + 4) * BST + c];
        }

        // split to hi/lo tf32 in registers
        uint32_t afh[4][4], afl[4][4];
#pragma unroll
        for (int mi = 0; mi < 4; mi++)
#pragma unroll
            for (int j = 0; j < 4; j++)
                split_tf32(arf[mi][j], afh[mi][j], afl[mi][j]);
        uint32_t bfh[8][2], bfl[8][2];
#pragma unroll
        for (int ni = 0; ni < 8; ni++)
#pragma unroll
            for (int j = 0; j < 2; j++)
                split_tf32(brf[ni][j], bfh[ni][j], bfl[ni][j]);

        // term-ordered MMAs: hh, hl, lh (lo*lo dropped)
#pragma unroll
        for (int mi = 0; mi < 4; mi++)
#pragma unroll
            for (int ni = 0; ni < 8; ni++)
                mma_tf32(acc[mi][ni], afh[mi][0], afh[mi][1], afh[mi][2], afh[mi][3],
                         bfh[ni][0], bfh[ni][1]);
#pragma unroll
        for (int mi = 0; mi < 4; mi++)
#pragma unroll
            for (int ni = 0; ni < 8; ni++)
                mma_tf32(acc[mi][ni], afh[mi][0], afh[mi][1], afh[mi][2], afh[mi][3],
                         bfl[ni][0], bfl[ni][1]);
#pragma unroll
        for (int mi = 0; mi < 4; mi++)
#pragma unroll
            for (int ni = 0; ni < 8; ni++)
                mma_tf32(acc[mi][ni], afl[mi][0], afl[mi][1], afl[mi][2], afl[mi][3],
                         bfh[ni][0], bfh[ni][1]);

        const int nk = i + 2;
        if (nk < 32) issue(nk % STAGES, nk * 8);
        cp_commit();
    }

    // Epilogue: bias + store; (c0,c1) at row, (c2,c3) at row+8
#pragma unroll
    for (int mi = 0; mi < 4; mi++) {
        const int r = row0 + warp_m + mi * 16 + g;
#pragma unroll
        for (int ni = 0; ni < 8; ni++) {
            const int c = col0 + warp_n + ni * 8 + t4 * 2;
            const float2 bb = *(const float2*)&bias[c];
            float2 o0, o1;
            o0.x = acc[mi][ni][0] + bb.x;
            o0.y = acc[mi][ni][1] + bb.y;
            o1.x = acc[mi][ni][2] + bb.x;
            o1.y = acc[mi][ni][3] + bb.y;
            *(float2*)&C[(size_t)r * Ncols + c]       = o0;
            *(float2*)&C[(size_t)(r + 8) * Ncols + c] = o1;
        }
    }
}

// ---------------------------------------------------------------------------
// Deformable sampling + per-head softmax + weighted sum. (unchanged from R4)
// ---------------------------------------------------------------------------
__global__ __launch_bounds__(256) void deform_sample(
    const float* __restrict__ refp)
{
    const int b = blockIdx.x;       // 0 .. M_TOTAL-1
    const int n = b / NQv;
    const int q = b - n * NQv;

    __shared__ float s_off[256];
    __shared__ float s_attn[128];
    __shared__ int   s_idx[8][16][4];
    __shared__ float s_w[8][16][4];

    const int tid = threadIdx.x;
    s_off[tid] = g_off[(size_t)b * 256 + tid];
    if (tid < 128) s_attn[tid] = g_attn[(size_t)b * 128 + tid];
    __syncthreads();

    const int m    = tid >> 5;   // head
    const int lane = tid & 31;
    const int k    = lane & 15;  // point id (lanes 16-31 mirror 0-15)

    float logit = s_attn[m * 16 + k];
    float mx = logit;
#pragma unroll
    for (int s = 8; s > 0; s >>= 1)
        mx = fmaxf(mx, __shfl_xor_sync(0xffffffffu, mx, s));
    float e = __expf(logit - mx);
    float ssum = e;
#pragma unroll
    for (int s = 8; s > 0; s >>= 1)
        ssum += __shfl_xor_sync(0xffffffffu, ssum, s);
    const float wk = e / ssum;

    if (lane < 16) {
        const int l = k >> 2;
        const int p = k & 3;
        const float ref0 = refp[q * 2 + 0];
        const float ref1 = refp[q * 2 + 1];

        const int oidx = ((l * 8 + m) * 4 + p) * 2;
        const float gy = ref0 + s_off[oidx + 0];
        const float gx = ref1 + s_off[oidx + 1];

        const int hw = 64 >> l;
        const int st = (16384 - (16384 >> (2 * l))) / 3;  // 0,4096,5120,5376

        const float scale = hw * 0.5f;
        const float x = gx * scale + (scale - 0.5f);
        const float y = gy * scale + (scale - 0.5f);
        const float x0f = floorf(x);
        const float y0f = floorf(y);
        const float wx = x - x0f;
        const float wy = y - y0f;
        const int x0 = (int)x0f;
        const int y0 = (int)y0f;
        const int x1 = x0 + 1;
        const int y1 = y0 + 1;

        const bool vx0 = (x0 >= 0) & (x0 < hw);
        const bool vx1 = (x1 >= 0) & (x1 < hw);
        const bool vy0 = (y0 >= 0) & (y0 < hw);
        const bool vy1 = (y1 >= 0) & (y1 < hw);

        const int xc0 = min(max(x0, 0), hw - 1);
        const int xc1 = min(max(x1, 0), hw - 1);
        const int yc0 = min(max(y0, 0), hw - 1);
        const int yc1 = min(max(y1, 0), hw - 1);

        int4 idx;
        idx.x = (st + yc0 * hw + xc0) * 256;
        idx.y = (st + yc0 * hw + xc1) * 256;
        idx.z = (st + yc1 * hw + xc0) * 256;
        idx.w = (st + yc1 * hw + xc1) * 256;

        float4 w;
        w.x = wk * (1.f - wx) * (1.f - wy) * (float)(vx0 & vy0);
        w.y = wk * wx * (1.f - wy)         * (float)(vx1 & vy0);
        w.z = wk * (1.f - wx) * wy         * (float)(vx0 & vy1);
        w.w = wk * wx * wy                 * (float)(vx1 & vy1);

        *(int4*)  &s_idx[m][k][0] = idx;
        *(float4*)&s_w[m][k][0]   = w;
    }
    __syncwarp();

    const int corner = lane >> 3;
    const int ch4    = lane & 7;
    const float* __restrict__ vb =
        g_values + (size_t)n * ((size_t)NQv * 256) + m * 32 + ch4 * 4;

    float4 acc = {0.f, 0.f, 0.f, 0.f};
#pragma unroll
    for (int kk = 0; kk < 16; kk++) {
        const int   id = s_idx[m][kk][corner];
        const float w  = s_w[m][kk][corner];
        const float4 v = *(const float4*)(vb + id);
        acc.x += w * v.x;
        acc.y += w * v.y;
        acc.z += w * v.z;
        acc.w += w * v.w;
    }

#pragma unroll
    for (int s = 8; s <= 16; s <<= 1) {
        acc.x += __shfl_xor_sync(0xffffffffu, acc.x, s);
        acc.y += __shfl_xor_sync(0xffffffffu, acc.y, s);
        acc.z += __shfl_xor_sync(0xffffffffu, acc.z, s);
        acc.w += __shfl_xor_sync(0xffffffffu, acc.w, s);
    }

    if (lane < 8)
        *(float4*)&g_sampled[(size_t)b * 256 + m * 32 + lane * 4] = acc;
}

// ---------------------------------------------------------------------------
extern "C" void kernel_launch(void* const* d_in, const int* in_sizes, int n_in,
                              void* d_out, int out_size)
{
    const float* hs     = (const float*)d_in[0];   // (4, 5440, 256)
    const float* pos    = (const float*)d_in[1];   // (5440, 256)
    const float* refp   = (const float*)d_in[2];   // (5440, 2)
    // d_in[3] = spatial_shapes (fixed, hardcoded)
    const float* W_off  = (const float*)d_in[4];
    const float* b_off  = (const float*)d_in[5];
    const float* W_attn = (const float*)d_in[6];
    const float* b_attn = (const float*)d_in[7];
    const float* W_val  = (const float*)d_in[8];
    const float* b_val  = (const float*)d_in[9];
    const float* W_out  = (const float*)d_in[10];
    const float* b_out  = (const float*)d_in[11];
    float* out = (float*)d_out;

    float *gh, *gv, *go, *ga, *gs;
    cudaGetSymbolAddress((void**)&gh, g_hpos);
    cudaGetSymbolAddress((void**)&gv, g_values);
    cudaGetSymbolAddress((void**)&go, g_off);
    cudaGetSymbolAddress((void**)&ga, g_attn);
    cudaGetSymbolAddress((void**)&gs, g_sampled);

    dim3 grid256(M_TOTAL / BM, 256 / BN);   // (170, 2)
    dim3 grid128(M_TOTAL / BM, 128 / BN);   // (170, 1)

    // hpos = hs + pos
    add_pos<<<M_TOTAL * 64 / 256, 256>>>(hs, pos, gh);
    // values = hs @ W_val + b_val
    gemm_tf32x3<<<grid256, 128>>>(hs, W_val, b_val, gv, 256);
    // off = hpos @ W_off + b_off
    gemm_tf32x3<<<grid256, 128>>>(gh, W_off, b_off, go, 256);
    // attn = hpos @ W_attn + b_attn
    gemm_tf32x3<<<grid128, 128>>>(gh, W_attn, b_attn, ga, 128);
    // sampling + softmax + weighted sum -> g_sampled
    deform_sample<<<M_TOTAL, 256>>>(refp);
    // out = g_sampled @ W_out + b_out
    gemm_tf32x3<<<grid256, 128>>>(gs, W_out, b_out, out, 256);
}

// round 7
// speedup vs baseline: 1.8191x; 1.0914x over previous
#include <cuda_runtime.h>
#include <cstddef>
#include <cstdint>

#define NQv    5440
#define NBATCH 4
#define M_TOTAL (NBATCH * NQv)   // 21760

// Scratch (allocation-free rule: __device__ globals)
__device__ float g_hpos   [(size_t)M_TOTAL * 256];
__device__ float g_values [(size_t)M_TOTAL * 256];
__device__ float g_off    [(size_t)M_TOTAL * 256];
__device__ float g_attn   [(size_t)M_TOTAL * 128];
__device__ float g_sampled[(size_t)M_TOTAL * 256];

// ---------------------------------------------------------------------------
// hs + pos (pos broadcast across batch)
// ---------------------------------------------------------------------------
__global__ __launch_bounds__(256) void add_pos(
    const float* __restrict__ hs, const float* __restrict__ pos,
    float* __restrict__ out)
{
    const int i = blockIdx.x * 256 + threadIdx.x;   // float4 index
    const int PQ = NQv * 64;                        // float4s per batch
    float4 a = ((const float4*)hs)[i];
    float4 p = ((const float4*)pos)[i % PQ];
    a.x += p.x; a.y += p.y; a.z += p.z; a.w += p.w;
    ((float4*)out)[i] = a;
}

// ---------------------------------------------------------------------------
// 3xTF32 tensor-core GEMM, cp.async staged, split-on-read:
//   C[M,Ncols] = A[M,256] @ B[256,Ncols] + bias
// Block 128x64, BK=8, 128 threads (4 warps), warp tile 64x32 (m16n8k8, 4x4).
// 3-stage cp.async ring of RAW fp32 tiles; hi/lo tf32 split in registers.
// Smaller warp tile than R5 -> ~140 regs -> 3 blocks/SM -> 12 warps/SM.
// ---------------------------------------------------------------------------
#define BM 128
#define BN 64
#define BK 8
#define AST 12    // (g*12+t4) mod 32 all-distinct -> conflict-free
#define BST 72    // (t4*72+g) mod 32 = t4*8+g all-distinct -> conflict-free
#define STAGES 3

__device__ __forceinline__ uint32_t f2tf32(float x) {
    uint32_t r;
    asm("cvt.rna.tf32.f32 %0, %1;" : "=r"(r) : "f"(x));
    return r;
}
__device__ __forceinline__ void split_tf32(float x, uint32_t& hi, uint32_t& lo) {
    hi = f2tf32(x);
    lo = f2tf32(x - __uint_as_float(hi));
}
__device__ __forceinline__ void mma_tf32(float d[4],
    uint32_t a0, uint32_t a1, uint32_t a2, uint32_t a3,
    uint32_t b0, uint32_t b1)
{
    asm volatile(
        "mma.sync.aligned.m16n8k8.row.col.f32.tf32.tf32.f32 "
        "{%0,%1,%2,%3}, {%4,%5,%6,%7}, {%8,%9}, {%0,%1,%2,%3};\n"
        : "+f"(d[0]), "+f"(d[1]), "+f"(d[2]), "+f"(d[3])
        : "r"(a0), "r"(a1), "r"(a2), "r"(a3), "r"(b0), "r"(b1));
}
__device__ __forceinline__ void cp_async16(uint32_t saddr, const void* g) {
    asm volatile("cp.async.cg.shared.global [%0], [%1], 16;\n"
                 :: "r"(saddr), "l"(g));
}
__device__ __forceinline__ void cp_commit() {
    asm volatile("cp.async.commit_group;\n");
}
template <int N>
__device__ __forceinline__ void cp_wait() {
    asm volatile("cp.async.wait_group %0;\n" :: "n"(N));
}

__global__ __launch_bounds__(128, 3) void gemm_tf32x3(
    const float* __restrict__ A, const float* __restrict__ B,
    const float* __restrict__ bias, float* __restrict__ C, int Ncols)
{
    __shared__ float As[STAGES][BM * AST];
    __shared__ float Bs[STAGES][BK * BST];

    const int tid    = threadIdx.x;
    const int lane   = tid & 31;
    const int wid    = tid >> 5;
    const int warp_m = (wid & 1) * 64;
    const int warp_n = (wid >> 1) * 32;
    const int g      = lane >> 2;
    const int t4     = lane & 3;

    const int row0 = blockIdx.x * BM;
    const int col0 = blockIdx.y * BN;

    // copy assignments: A: 128 rows x 8 k, 1 row/thread (2x16B).
    //                   B: 8 rows x 64 cols, 4 floats/thread (1x16B).
    const int ar  = tid;
    const int brr = tid >> 4;          // 0..7
    const int bcc = (tid & 15) * 4;    // 0..60
    const float* Ag = A + (size_t)(row0 + ar) * 256;
    const float* Bg = B + (size_t)brr * Ncols + col0 + bcc;

    uint32_t sA[STAGES], sB[STAGES];
#pragma unroll
    for (int s = 0; s < STAGES; s++) {
        sA[s] = (uint32_t)__cvta_generic_to_shared(&As[s][ar * AST]);
        sB[s] = (uint32_t)__cvta_generic_to_shared(&Bs[s][brr * BST + bcc]);
    }

    auto issue = [&](int s, int k0) {
        cp_async16(sA[s],      Ag + k0);
        cp_async16(sA[s] + 16, Ag + k0 + 4);
        cp_async16(sB[s], Bg + (size_t)k0 * Ncols);
    };

    float acc[4][4][4];
#pragma unroll
    for (int mi = 0; mi < 4; mi++)
#pragma unroll
        for (int ni = 0; ni < 4; ni++)
#pragma unroll
            for (int j = 0; j < 4; j++) acc[mi][ni][j] = 0.f;

    issue(0, 0);  cp_commit();
    issue(1, 8);  cp_commit();

    for (int i = 0; i < 32; i++) {
        cp_wait<1>();
        __syncthreads();
        const int st = i % STAGES;
        const float* as_ = As[st];
        const float* bs_ = Bs[st];

        // fragment loads (raw fp32)
        float arf[4][4];
#pragma unroll
        for (int mi = 0; mi < 4; mi++) {
            const int r = warp_m + mi * 16 + g;
            arf[mi][0] = as_[r * AST + t4];
            arf[mi][1] = as_[(r + 8) * AST + t4];
            arf[mi][2] = as_[r * AST + t4 + 4];
            arf[mi][3] = as_[(r + 8) * AST + t4 + 4];
        }
        float brf[4][2];
#pragma unroll
        for (int ni = 0; ni < 4; ni++) {
            const int c = warp_n + ni * 8 + g;
            brf[ni][0] = bs_[t4 * BST + c];
            brf[ni][1] = bs_[(t4 + 4) * BST + c];
        }

        // split to hi/lo tf32 in registers
        uint32_t afh[4][4], afl[4][4];
#pragma unroll
        for (int mi = 0; mi < 4; mi++)
#pragma unroll
            for (int j = 0; j < 4; j++)
                split_tf32(arf[mi][j], afh[mi][j], afl[mi][j]);
        uint32_t bfh[4][2], bfl[4][2];
#pragma unroll
        for (int ni = 0; ni < 4; ni++)
#pragma unroll
            for (int j = 0; j < 2; j++)
                split_tf32(brf[ni][j], bfh[ni][j], bfl[ni][j]);

        // 3 terms: hh, hl, lh (lo*lo dropped)
#pragma unroll
        for (int mi = 0; mi < 4; mi++)
#pragma unroll
            for (int ni = 0; ni < 4; ni++)
                mma_tf32(acc[mi][ni], afh[mi][0], afh[mi][1], afh[mi][2], afh[mi][3],
                         bfh[ni][0], bfh[ni][1]);
#pragma unroll
        for (int mi = 0; mi < 4; mi++)
#pragma unroll
            for (int ni = 0; ni < 4; ni++)
                mma_tf32(acc[mi][ni], afh[mi][0], afh[mi][1], afh[mi][2], afh[mi][3],
                         bfl[ni][0], bfl[ni][1]);
#pragma unroll
        for (int mi = 0; mi < 4; mi++)
#pragma unroll
            for (int ni = 0; ni < 4; ni++)
                mma_tf32(acc[mi][ni], afl[mi][0], afl[mi][1], afl[mi][2], afl[mi][3],
                         bfh[ni][0], bfh[ni][1]);

        const int nk = i + 2;
        if (nk < 32) issue(nk % STAGES, nk * 8);
        cp_commit();
    }

    // Epilogue: bias + store; (c0,c1) at row, (c2,c3) at row+8
#pragma unroll
    for (int mi = 0; mi < 4; mi++) {
        const int r = row0 + warp_m + mi * 16 + g;
#pragma unroll
        for (int ni = 0; ni < 4; ni++) {
            const int c = col0 + warp_n + ni * 8 + t4 * 2;
            const float2 bb = *(const float2*)&bias[c];
            float2 o0, o1;
            o0.x = acc[mi][ni][0] + bb.x;
            o0.y = acc[mi][ni][1] + bb.y;
            o1.x = acc[mi][ni][2] + bb.x;
            o1.y = acc[mi][ni][3] + bb.y;
            *(float2*)&C[(size_t)r * Ncols + c]       = o0;
            *(float2*)&C[(size_t)(r + 8) * Ncols + c] = o1;
        }
    }
}

// ---------------------------------------------------------------------------
// Deformable sampling + per-head softmax + weighted sum. (unchanged)
// ---------------------------------------------------------------------------
__global__ __launch_bounds__(256) void deform_sample(
    const float* __restrict__ refp)
{
    const int b = blockIdx.x;       // 0 .. M_TOTAL-1
    const int n = b / NQv;
    const int q = b - n * NQv;

    __shared__ float s_off[256];
    __shared__ float s_attn[128];
    __shared__ int   s_idx[8][16][4];
    __shared__ float s_w[8][16][4];

    const int tid = threadIdx.x;
    s_off[tid] = g_off[(size_t)b * 256 + tid];
    if (tid < 128) s_attn[tid] = g_attn[(size_t)b * 128 + tid];
    __syncthreads();

    const int m    = tid >> 5;   // head
    const int lane = tid & 31;
    const int k    = lane & 15;  // point id (lanes 16-31 mirror 0-15)

    float logit = s_attn[m * 16 + k];
    float mx = logit;
#pragma unroll
    for (int s = 8; s > 0; s >>= 1)
        mx = fmaxf(mx, __shfl_xor_sync(0xffffffffu, mx, s));
    float e = __expf(logit - mx);
    float ssum = e;
#pragma unroll
    for (int s = 8; s > 0; s >>= 1)
        ssum += __shfl_xor_sync(0xffffffffu, ssum, s);
    const float wk = e / ssum;

    if (lane < 16) {
        const int l = k >> 2;
        const int p = k & 3;
        const float ref0 = refp[q * 2 + 0];
        const float ref1 = refp[q * 2 + 1];

        const int oidx = ((l * 8 + m) * 4 + p) * 2;
        const float gy = ref0 + s_off[oidx + 0];
        const float gx = ref1 + s_off[oidx + 1];

        const int hw = 64 >> l;
        const int st = (16384 - (16384 >> (2 * l))) / 3;  // 0,4096,5120,5376

        const float scale = hw * 0.5f;
        const float x = gx * scale + (scale - 0.5f);
        const float y = gy * scale + (scale - 0.5f);
        const float x0f = floorf(x);
        const float y0f = floorf(y);
        const float wx = x - x0f;
        const float wy = y - y0f;
        const int x0 = (int)x0f;
        const int y0 = (int)y0f;
        const int x1 = x0 + 1;
        const int y1 = y0 + 1;

        const bool vx0 = (x0 >= 0) & (x0 < hw);
        const bool vx1 = (x1 >= 0) & (x1 < hw);
        const bool vy0 = (y0 >= 0) & (y0 < hw);
        const bool vy1 = (y1 >= 0) & (y1 < hw);

        const int xc0 = min(max(x0, 0), hw - 1);
        const int xc1 = min(max(x1, 0), hw - 1);
        const int yc0 = min(max(y0, 0), hw - 1);
        const int yc1 = min(max(y1, 0), hw - 1);

        int4 idx;
        idx.x = (st + yc0 * hw + xc0) * 256;
        idx.y = (st + yc0 * hw + xc1) * 256;
        idx.z = (st + yc1 * hw + xc0) * 256;
        idx.w = (st + yc1 * hw + xc1) * 256;

        float4 w;
        w.x = wk * (1.f - wx) * (1.f - wy) * (float)(vx0 & vy0);
        w.y = wk * wx * (1.f - wy)         * (float)(vx1 & vy0);
        w.z = wk * (1.f - wx) * wy         * (float)(vx0 & vy1);
        w.w = wk * wx * wy                 * (float)(vx1 & vy1);

        *(int4*)  &s_idx[m][k][0] = idx;
        *(float4*)&s_w[m][k][0]   = w;
    }
    __syncwarp();

    const int corner = lane >> 3;
    const int ch4    = lane & 7;
    const float* __restrict__ vb =
        g_values + (size_t)n * ((size_t)NQv * 256) + m * 32 + ch4 * 4;

    float4 acc = {0.f, 0.f, 0.f, 0.f};
#pragma unroll
    for (int kk = 0; kk < 16; kk++) {
        const int   id = s_idx[m][kk][corner];
        const float w  = s_w[m][kk][corner];
        const float4 v = *(const float4*)(vb + id);
        acc.x += w * v.x;
        acc.y += w * v.y;
        acc.z += w * v.z;
        acc.w += w * v.w;
    }

#pragma unroll
    for (int s = 8; s <= 16; s <<= 1) {
        acc.x += __shfl_xor_sync(0xffffffffu, acc.x, s);
        acc.y += __shfl_xor_sync(0xffffffffu, acc.y, s);
        acc.z += __shfl_xor_sync(0xffffffffu, acc.z, s);
        acc.w += __shfl_xor_sync(0xffffffffu, acc.w, s);
    }

    if (lane < 8)
        *(float4*)&g_sampled[(size_t)b * 256 + m * 32 + lane * 4] = acc;
}

// ---------------------------------------------------------------------------
extern "C" void kernel_launch(void* const* d_in, const int* in_sizes, int n_in,
                              void* d_out, int out_size)
{
    const float* hs     = (const float*)d_in[0];   // (4, 5440, 256)
    const float* pos    = (const float*)d_in[1];   // (5440, 256)
    const float* refp   = (const float*)d_in[2];   // (5440, 2)
    // d_in[3] = spatial_shapes (fixed, hardcoded)
    const float* W_off  = (const float*)d_in[4];
    const float* b_off  = (const float*)d_in[5];
    const float* W_attn = (const float*)d_in[6];
    const float* b_attn = (const float*)d_in[7];
    const float* W_val  = (const float*)d_in[8];
    const float* b_val  = (const float*)d_in[9];
    const float* W_out  = (const float*)d_in[10];
    const float* b_out  = (const float*)d_in[11];
    float* out = (float*)d_out;

    float *gh, *gv, *go, *ga, *gs;
    cudaGetSymbolAddress((void**)&gh, g_hpos);
    cudaGetSymbolAddress((void**)&gv, g_values);
    cudaGetSymbolAddress((void**)&go, g_off);
    cudaGetSymbolAddress((void**)&ga, g_attn);
    cudaGetSymbolAddress((void**)&gs, g_sampled);

    dim3 grid256(M_TOTAL / BM, 256 / BN);   // (170, 4)
    dim3 grid128(M_TOTAL / BM, 128 / BN);   // (170, 2)

    // hpos = hs + pos
    add_pos<<<M_TOTAL * 64 / 256, 256>>>(hs, pos, gh);
    // values = hs @ W_val + b_val
    gemm_tf32x3<<<grid256, 128>>>(hs, W_val, b_val, gv, 256);
    // off = hpos @ W_off + b_off
    gemm_tf32x3<<<grid256, 128>>>(gh, W_off, b_off, go, 256);
    // attn = hpos @ W_attn + b_attn
    gemm_tf32x3<<<grid128, 128>>>(gh, W_attn, b_attn, ga, 128);
    // sampling + softmax + weighted sum -> g_sampled
    deform_sample<<<M_TOTAL, 256>>>(refp);
    // out = g_sampled @ W_out + b_out
    gemm_tf32x3<<<grid256, 128>>>(gs, W_out, b_out, out, 256);
}

// round 8
// speedup vs baseline: 2.1719x; 1.1939x over previous
#include <cuda_runtime.h>
#include <cuda_bf16.h>
#include <cstddef>
#include <cstdint>

#define NQv    5440
#define NBATCH 4
#define M_TOTAL (NBATCH * NQv)   // 21760

// ---------------- scratch (__device__ globals, allocation-free rule) --------
__device__ __nv_bfloat16 g_hs_hi [(size_t)M_TOTAL * 256];
__device__ __nv_bfloat16 g_hs_lo [(size_t)M_TOTAL * 256];
__device__ __nv_bfloat16 g_hp_hi [(size_t)M_TOTAL * 256];
__device__ __nv_bfloat16 g_hp_lo [(size_t)M_TOTAL * 256];
__device__ __nv_bfloat16 g_sp_hi [(size_t)M_TOTAL * 256];
__device__ __nv_bfloat16 g_sp_lo [(size_t)M_TOTAL * 256];
__device__ __nv_bfloat16 g_Wval_hi[256 * 256], g_Wval_lo[256 * 256];
__device__ __nv_bfloat16 g_Wcat_hi[384 * 256], g_Wcat_lo[384 * 256];
__device__ __nv_bfloat16 g_Wout_hi[256 * 256], g_Wout_lo[256 * 256];
__device__ float g_bcat  [384];
__device__ float g_values[(size_t)M_TOTAL * 256];
__device__ float g_cat   [(size_t)M_TOTAL * 384];   // [off 256 | attn 128]

__device__ __forceinline__ void split1(float x, __nv_bfloat16& h, __nv_bfloat16& l) {
    h = __float2bfloat16(x);
    l = __float2bfloat16(x - __bfloat162float(h));
}

// ---------------------------------------------------------------------------
// prep_w: transpose + split all weights; build cat weight (off|attn) + bias
// ---------------------------------------------------------------------------
__global__ __launch_bounds__(256) void prep_w(
    const float* __restrict__ Wval, const float* __restrict__ Woff,
    const float* __restrict__ Wattn, const float* __restrict__ Wout,
    const float* __restrict__ boff, const float* __restrict__ battn)
{
    const int i = blockIdx.x * 256 + threadIdx.x;
    if (i < 65536) {                      // Wval: Wt[n][k] = W[k][n]
        const int n = i >> 8, k = i & 255;
        __nv_bfloat16 h, l;
        split1(Wval[k * 256 + n], h, l);
        g_Wval_hi[n * 256 + k] = h;
        g_Wval_lo[n * 256 + k] = l;
    } else if (i < 65536 + 98304) {       // Wcat: n<256 from Woff, else Wattn
        const int j = i - 65536;
        const int n = j >> 8, k = j & 255;
        const float v = (n < 256) ? Woff[k * 256 + n] : Wattn[k * 128 + (n - 256)];
        __nv_bfloat16 h, l;
        split1(v, h, l);
        g_Wcat_hi[n * 256 + k] = h;
        g_Wcat_lo[n * 256 + k] = l;
    } else if (i < 229376) {              // Wout
        const int j = i - 163840;
        const int n = j >> 8, k = j & 255;
        __nv_bfloat16 h, l;
        split1(Wout[k * 256 + n], h, l);
        g_Wout_hi[n * 256 + k] = h;
        g_Wout_lo[n * 256 + k] = l;
    }
    if (i < 384) g_bcat[i] = (i < 256) ? boff[i] : battn[i - 256];
}

// ---------------------------------------------------------------------------
// prep_a: split hs -> hs_hi/lo ; split hs+pos -> hp_hi/lo (one pass)
// ---------------------------------------------------------------------------
__device__ __forceinline__ void split_store4(float4 v,
    __nv_bfloat16* ph, __nv_bfloat16* pl)
{
    __nv_bfloat16 h0, l0, h1, l1, h2, l2, h3, l3;
    split1(v.x, h0, l0); split1(v.y, h1, l1);
    split1(v.z, h2, l2); split1(v.w, h3, l3);
    ushort4 H = {__bfloat16_as_ushort(h0), __bfloat16_as_ushort(h1),
                 __bfloat16_as_ushort(h2), __bfloat16_as_ushort(h3)};
    ushort4 L = {__bfloat16_as_ushort(l0), __bfloat16_as_ushort(l1),
                 __bfloat16_as_ushort(l2), __bfloat16_as_ushort(l3)};
    *(ushort4*)ph = H;
    *(ushort4*)pl = L;
}

__global__ __launch_bounds__(256) void prep_a(
    const float* __restrict__ hs, const float* __restrict__ pos)
{
    const int i  = blockIdx.x * 256 + threadIdx.x;   // float4 index
    const int PQ = NQv * 64;
    float4 a = ((const float4*)hs)[i];
    float4 p = ((const float4*)pos)[i % PQ];
    split_store4(a, g_hs_hi + 4 * (size_t)i, g_hs_lo + 4 * (size_t)i);
    a.x += p.x; a.y += p.y; a.z += p.z; a.w += p.w;
    split_store4(a, g_hp_hi + 4 * (size_t)i, g_hp_lo + 4 * (size_t)i);
}

// ---------------------------------------------------------------------------
// bf16x3 GEMM: C[M,Ncols] = (Ah+Al)[M,256] @ (Bh+Bl)^T[Ncols,256] + bias
// (B given pre-transposed [n][k]). 3 terms: AhBh + AhBl + AlBh.
// Block 128x64, BK=16, 128 threads (4 warps), warp tile 64x32.
// mma.m16n8k16.bf16, ldmatrix.x4 for A frags, 3-stage cp.async ring.
// smem words (f32-sized = 2 bf16): A [row][20] (hi w0-7, lo w8-15, pad 4),
//                                  B [n][20] same; stride 20 conflict-free.
// ---------------------------------------------------------------------------
#define BM 128
#define BN 64
#define BKB 16
#define WST 20
#define STAGES 3

__device__ __forceinline__ void mma_bf16(float d[4],
    uint32_t a0, uint32_t a1, uint32_t a2, uint32_t a3,
    uint32_t b0, uint32_t b1)
{
    asm volatile(
        "mma.sync.aligned.m16n8k16.row.col.f32.bf16.bf16.f32 "
        "{%0,%1,%2,%3}, {%4,%5,%6,%7}, {%8,%9}, {%0,%1,%2,%3};\n"
        : "+f"(d[0]), "+f"(d[1]), "+f"(d[2]), "+f"(d[3])
        : "r"(a0), "r"(a1), "r"(a2), "r"(a3), "r"(b0), "r"(b1));
}
__device__ __forceinline__ void ldmx4(uint32_t r[4], uint32_t addr) {
    asm volatile(
        "ldmatrix.sync.aligned.m8n8.x4.shared.b16 {%0,%1,%2,%3}, [%4];\n"
        : "=r"(r[0]), "=r"(r[1]), "=r"(r[2]), "=r"(r[3]) : "r"(addr));
}
__device__ __forceinline__ void cp_async16(uint32_t saddr, const void* g) {
    asm volatile("cp.async.cg.shared.global [%0], [%1], 16;\n"
                 :: "r"(saddr), "l"(g));
}
__device__ __forceinline__ void cp_commit() {
    asm volatile("cp.async.commit_group;\n");
}
template <int N>
__device__ __forceinline__ void cp_wait() {
    asm volatile("cp.async.wait_group %0;\n" :: "n"(N));
}

__global__ __launch_bounds__(128, 3) void gemm_bf16x3(
    const __nv_bfloat16* __restrict__ Ah, const __nv_bfloat16* __restrict__ Al,
    const __nv_bfloat16* __restrict__ Bh, const __nv_bfloat16* __restrict__ Bl,
    const float* __restrict__ bias, float* __restrict__ C, int Ncols)
{
    __shared__ uint32_t As[STAGES][BM * WST];
    __shared__ uint32_t Bs[STAGES][BN * WST];

    const int tid    = threadIdx.x;
    const int lane   = tid & 31;
    const int wid    = tid >> 5;
    const int warp_m = (wid & 1) * 64;
    const int warp_n = (wid >> 1) * 32;
    const int g      = lane >> 2;
    const int t4     = lane & 3;

    const int row0 = blockIdx.x * BM;
    const int col0 = blockIdx.y * BN;

    // loaders: A: row tid (hi 2x16B + lo 2x16B). B: row tid>>1, tid&1 -> hi/lo.
    const int rA = tid;
    const __nv_bfloat16* AgH = Ah + (size_t)(row0 + rA) * 256;
    const __nv_bfloat16* AgL = Al + (size_t)(row0 + rA) * 256;
    const int nB  = tid >> 1;
    const int loB = tid & 1;
    const __nv_bfloat16* Bg = (loB ? Bl : Bh) + (size_t)(col0 + nB) * 256;

    uint32_t sA[STAGES], sB[STAGES];
#pragma unroll
    for (int s = 0; s < STAGES; s++) {
        sA[s] = (uint32_t)__cvta_generic_to_shared(&As[s][rA * WST]);
        sB[s] = (uint32_t)__cvta_generic_to_shared(&Bs[s][nB * WST + loB * 8]);
    }

    auto issue = [&](int s, int k0) {
        cp_async16(sA[s] +  0, AgH + k0);
        cp_async16(sA[s] + 16, AgH + k0 + 8);
        cp_async16(sA[s] + 32, AgL + k0);
        cp_async16(sA[s] + 48, AgL + k0 + 8);
        cp_async16(sB[s] +  0, Bg + k0);
        cp_async16(sB[s] + 16, Bg + k0 + 8);
    };

    float acc[4][4][4];
#pragma unroll
    for (int mi = 0; mi < 4; mi++)
#pragma unroll
        for (int ni = 0; ni < 4; ni++)
#pragma unroll
            for (int j = 0; j < 4; j++) acc[mi][ni][j] = 0.f;

    issue(0, 0);   cp_commit();
    issue(1, 16);  cp_commit();

    // ldmatrix lane address pattern (words): (r0 + (lane&15))*WST + (lane>>4)*4
    const int lrow = lane & 15;
    const int lwof = (lane >> 4) * 4;

    for (int i = 0; i < 16; i++) {
        cp_wait<1>();
        __syncthreads();
        const int st = i % STAGES;
        const uint32_t* bs_ = Bs[st];
        const uint32_t a_base = (uint32_t)__cvta_generic_to_shared(&As[st][0]);

        uint32_t afh[4][4], afl[4][4];
#pragma unroll
        for (int mi = 0; mi < 4; mi++) {
            const uint32_t addr =
                a_base + ((warp_m + mi * 16 + lrow) * WST + lwof) * 4;
            ldmx4(afh[mi], addr);
            ldmx4(afl[mi], addr + 32);
        }
        uint32_t bfh[4][2], bfl[4][2];
#pragma unroll
        for (int ni = 0; ni < 4; ni++) {
            const int n = warp_n + ni * 8 + g;
            bfh[ni][0] = bs_[n * WST + t4];
            bfh[ni][1] = bs_[n * WST + t4 + 4];
            bfl[ni][0] = bs_[n * WST + 8 + t4];
            bfl[ni][1] = bs_[n * WST + 12 + t4];
        }

#pragma unroll
        for (int mi = 0; mi < 4; mi++)
#pragma unroll
            for (int ni = 0; ni < 4; ni++)
                mma_bf16(acc[mi][ni], afh[mi][0], afh[mi][1], afh[mi][2], afh[mi][3],
                         bfh[ni][0], bfh[ni][1]);
#pragma unroll
        for (int mi = 0; mi < 4; mi++)
#pragma unroll
            for (int ni = 0; ni < 4; ni++)
                mma_bf16(acc[mi][ni], afh[mi][0], afh[mi][1], afh[mi][2], afh[mi][3],
                         bfl[ni][0], bfl[ni][1]);
#pragma unroll
        for (int mi = 0; mi < 4; mi++)
#pragma unroll
            for (int ni = 0; ni < 4; ni++)
                mma_bf16(acc[mi][ni], afl[mi][0], afl[mi][1], afl[mi][2], afl[mi][3],
                         bfh[ni][0], bfh[ni][1]);

        const int nk = i + 2;
        if (nk < 16) issue(nk % STAGES, nk * 16);
        cp_commit();
    }

    // Epilogue: bias + store; (c0,c1) at row, (c2,c3) at row+8
#pragma unroll
    for (int mi = 0; mi < 4; mi++) {
        const int r = row0 + warp_m + mi * 16 + g;
#pragma unroll
        for (int ni = 0; ni < 4; ni++) {
            const int c = col0 + warp_n + ni * 8 + t4 * 2;
            const float2 bb = *(const float2*)&bias[c];
            float2 o0, o1;
            o0.x = acc[mi][ni][0] + bb.x;
            o0.y = acc[mi][ni][1] + bb.y;
            o1.x = acc[mi][ni][2] + bb.x;
            o1.y = acc[mi][ni][3] + bb.y;
            *(float2*)&C[(size_t)r * Ncols + c]       = o0;
            *(float2*)&C[(size_t)(r + 8) * Ncols + c] = o1;
        }
    }
}

// ---------------------------------------------------------------------------
// Deformable sampling + per-head softmax + weighted sum.
// Reads off/attn from g_cat (stride 384); writes pre-split bf16 output.
// ---------------------------------------------------------------------------
__global__ __launch_bounds__(256) void deform_sample(
    const float* __restrict__ refp)
{
    const int b = blockIdx.x;       // 0 .. M_TOTAL-1
    const int n = b / NQv;
    const int q = b - n * NQv;

    __shared__ float s_off[256];
    __shared__ float s_attn[128];
    __shared__ int   s_idx[8][16][4];
    __shared__ float s_w[8][16][4];

    const int tid = threadIdx.x;
    s_off[tid] = g_cat[(size_t)b * 384 + tid];
    if (tid < 128) s_attn[tid] = g_cat[(size_t)b * 384 + 256 + tid];
    __syncthreads();

    const int m    = tid >> 5;   // head
    const int lane = tid & 31;
    const int k    = lane & 15;  // point id (lanes 16-31 mirror 0-15)

    float logit = s_attn[m * 16 + k];
    float mx = logit;
#pragma unroll
    for (int s = 8; s > 0; s >>= 1)
        mx = fmaxf(mx, __shfl_xor_sync(0xffffffffu, mx, s));
    float e = __expf(logit - mx);
    float ssum = e;
#pragma unroll
    for (int s = 8; s > 0; s >>= 1)
        ssum += __shfl_xor_sync(0xffffffffu, ssum, s);
    const float wk = e / ssum;

    if (lane < 16) {
        const int l = k >> 2;
        const int p = k & 3;
        const float ref0 = refp[q * 2 + 0];
        const float ref1 = refp[q * 2 + 1];

        const int oidx = ((l * 8 + m) * 4 + p) * 2;
        const float gy = ref0 + s_off[oidx + 0];
        const float gx = ref1 + s_off[oidx + 1];

        const int hw = 64 >> l;
        const int st = (16384 - (16384 >> (2 * l))) / 3;  // 0,4096,5120,5376

        const float scale = hw * 0.5f;
        const float x = gx * scale + (scale - 0.5f);
        const float y = gy * scale + (scale - 0.5f);
        const float x0f = floorf(x);
        const float y0f = floorf(y);
        const float wx = x - x0f;
        const float wy = y - y0f;
        const int x0 = (int)x0f;
        const int y0 = (int)y0f;
        const int x1 = x0 + 1;
        const int y1 = y0 + 1;

        const bool vx0 = (x0 >= 0) & (x0 < hw);
        const bool vx1 = (x1 >= 0) & (x1 < hw);
        const bool vy0 = (y0 >= 0) & (y0 < hw);
        const bool vy1 = (y1 >= 0) & (y1 < hw);

        const int xc0 = min(max(x0, 0), hw - 1);
        const int xc1 = min(max(x1, 0), hw - 1);
        const int yc0 = min(max(y0, 0), hw - 1);
        const int yc1 = min(max(y1, 0), hw - 1);

        int4 idx;
        idx.x = (st + yc0 * hw + xc0) * 256;
        idx.y = (st + yc0 * hw + xc1) * 256;
        idx.z = (st + yc1 * hw + xc0) * 256;
        idx.w = (st + yc1 * hw + xc1) * 256;

        float4 w;
        w.x = wk * (1.f - wx) * (1.f - wy) * (float)(vx0 & vy0);
        w.y = wk * wx * (1.f - wy)         * (float)(vx1 & vy0);
        w.z = wk * (1.f - wx) * wy         * (float)(vx0 & vy1);
        w.w = wk * wx * wy                 * (float)(vx1 & vy1);

        *(int4*)  &s_idx[m][k][0] = idx;
        *(float4*)&s_w[m][k][0]   = w;
    }
    __syncwarp();

    const int corner = lane >> 3;
    const int ch4    = lane & 7;
    const float* __restrict__ vb =
        g_values + (size_t)n * ((size_t)NQv * 256) + m * 32 + ch4 * 4;

    float4 acc = {0.f, 0.f, 0.f, 0.f};
#pragma unroll
    for (int kk = 0; kk < 16; kk++) {
        const int   id = s_idx[m][kk][corner];
        const float w  = s_w[m][kk][corner];
        const float4 v = *(const float4*)(vb + id);
        acc.x += w * v.x;
        acc.y += w * v.y;
        acc.z += w * v.z;
        acc.w += w * v.w;
    }

#pragma unroll
    for (int s = 8; s <= 16; s <<= 1) {
        acc.x += __shfl_xor_sync(0xffffffffu, acc.x, s);
        acc.y += __shfl_xor_sync(0xffffffffu, acc.y, s);
        acc.z += __shfl_xor_sync(0xffffffffu, acc.z, s);
        acc.w += __shfl_xor_sync(0xffffffffu, acc.w, s);
    }

    if (lane < 8) {
        const size_t o = (size_t)b * 256 + m * 32 + lane * 4;
        split_store4(acc, g_sp_hi + o, g_sp_lo + o);
    }
}

// ---------------------------------------------------------------------------
extern "C" void kernel_launch(void* const* d_in, const int* in_sizes, int n_in,
                              void* d_out, int out_size)
{
    const float* hs     = (const float*)d_in[0];   // (4, 5440, 256)
    const float* pos    = (const float*)d_in[1];   // (5440, 256)
    const float* refp   = (const float*)d_in[2];   // (5440, 2)
    // d_in[3] = spatial_shapes (fixed, hardcoded)
    const float* W_off  = (const float*)d_in[4];
    const float* b_off  = (const float*)d_in[5];
    const float* W_attn = (const float*)d_in[6];
    const float* b_attn = (const float*)d_in[7];
    const float* W_val  = (const float*)d_in[8];
    const float* b_val  = (const float*)d_in[9];
    const float* W_out  = (const float*)d_in[10];
    const float* b_out  = (const float*)d_in[11];
    float* out = (float*)d_out;

    __nv_bfloat16 *hsh, *hsl, *hph, *hpl, *sph, *spl;
    __nv_bfloat16 *wvh, *wvl, *wch, *wcl, *woh, *wol;
    float *gv, *gc, *bc;
    cudaGetSymbolAddress((void**)&hsh, g_hs_hi);
    cudaGetSymbolAddress((void**)&hsl, g_hs_lo);
    cudaGetSymbolAddress((void**)&hph, g_hp_hi);
    cudaGetSymbolAddress((void**)&hpl, g_hp_lo);
    cudaGetSymbolAddress((void**)&sph, g_sp_hi);
    cudaGetSymbolAddress((void**)&spl, g_sp_lo);
    cudaGetSymbolAddress((void**)&wvh, g_Wval_hi);
    cudaGetSymbolAddress((void**)&wvl, g_Wval_lo);
    cudaGetSymbolAddress((void**)&wch, g_Wcat_hi);
    cudaGetSymbolAddress((void**)&wcl, g_Wcat_lo);
    cudaGetSymbolAddress((void**)&woh, g_Wout_hi);
    cudaGetSymbolAddress((void**)&wol, g_Wout_lo);
    cudaGetSymbolAddress((void**)&gv, g_values);
    cudaGetSymbolAddress((void**)&gc, g_cat);
    cudaGetSymbolAddress((void**)&bc, g_bcat);

    // prep
    prep_w<<<896, 256>>>(W_val, W_off, W_attn, W_out, b_off, b_attn);
    prep_a<<<M_TOTAL * 64 / 256, 256>>>(hs, pos);

    dim3 gridV(M_TOTAL / BM, 256 / BN);   // (170, 4)
    dim3 gridC(M_TOTAL / BM, 384 / BN);   // (170, 6)

    // values = hs @ W_val + b_val
    gemm_bf16x3<<<gridV, 128>>>(hsh, hsl, wvh, wvl, b_val, gv, 256);
    // [off|attn] = hpos @ Wcat + bcat
    gemm_bf16x3<<<gridC, 128>>>(hph, hpl, wch, wcl, bc, gc, 384);
    // sampling + softmax + weighted sum -> g_sp (pre-split bf16)
    deform_sample<<<M_TOTAL, 256>>>(refp);
    // out = sampled @ W_out + b_out
    gemm_bf16x3<<<gridV, 128>>>(sph, spl, woh, wol, b_out, out, 256);
}

// round 10
// speedup vs baseline: 2.2868x; 1.0529x over previous
#include <cuda_runtime.h>
#include <cuda_bf16.h>
#include <cuda_fp16.h>
#include <cstddef>
#include <cstdint>

#define NQv    5440
#define NBATCH 4
#define M_TOTAL (NBATCH * NQv)   // 21760

// ---------------- scratch (__device__ globals, allocation-free rule) --------
__device__ __nv_bfloat16 g_hs_hi [(size_t)M_TOTAL * 256];
__device__ __nv_bfloat16 g_hs_lo [(size_t)M_TOTAL * 256];
__device__ __nv_bfloat16 g_hp_hi [(size_t)M_TOTAL * 256];
__device__ __nv_bfloat16 g_hp_lo [(size_t)M_TOTAL * 256];
__device__ __nv_bfloat16 g_sp_hi [(size_t)M_TOTAL * 256];
__device__ __nv_bfloat16 g_sp_lo [(size_t)M_TOTAL * 256];
__device__ __nv_bfloat16 g_Wval_hi[256 * 256], g_Wval_lo[256 * 256];
__device__ __nv_bfloat16 g_Wcat_hi[384 * 256], g_Wcat_lo[384 * 256];
__device__ __nv_bfloat16 g_Wout_hi[256 * 256], g_Wout_lo[256 * 256];
__device__ float  g_bcat  [384];
__device__ __half g_valh  [(size_t)M_TOTAL * 256];
__device__ float  g_cat   [(size_t)M_TOTAL * 384];   // [off 256 | attn 128]

__device__ __forceinline__ void split1(float x, __nv_bfloat16& h, __nv_bfloat16& l) {
    h = __float2bfloat16(x);
    l = __float2bfloat16(x - __bfloat162float(h));
}

// ---------------------------------------------------------------------------
// prep_w: transpose + split all weights; build cat weight (off|attn) + bias
// ---------------------------------------------------------------------------
__global__ __launch_bounds__(256) void prep_w(
    const float* __restrict__ Wval, const float* __restrict__ Woff,
    const float* __restrict__ Wattn, const float* __restrict__ Wout,
    const float* __restrict__ boff, const float* __restrict__ battn)
{
    const int i = blockIdx.x * 256 + threadIdx.x;
    if (i < 65536) {                      // Wval: Wt[n][k] = W[k][n]
        const int n = i >> 8, k = i & 255;
        __nv_bfloat16 h, l;
        split1(Wval[k * 256 + n], h, l);
        g_Wval_hi[n * 256 + k] = h;
        g_Wval_lo[n * 256 + k] = l;
    } else if (i < 65536 + 98304) {       // Wcat: n<256 from Woff, else Wattn
        const int j = i - 65536;
        const int n = j >> 8, k = j & 255;
        const float v = (n < 256) ? Woff[k * 256 + n] : Wattn[k * 128 + (n - 256)];
        __nv_bfloat16 h, l;
        split1(v, h, l);
        g_Wcat_hi[n * 256 + k] = h;
        g_Wcat_lo[n * 256 + k] = l;
    } else if (i < 229376) {              // Wout
        const int j = i - 163840;
        const int n = j >> 8, k = j & 255;
        __nv_bfloat16 h, l;
        split1(Wout[k * 256 + n], h, l);
        g_Wout_hi[n * 256 + k] = h;
        g_Wout_lo[n * 256 + k] = l;
    }
    if (i < 384) g_bcat[i] = (i < 256) ? boff[i] : battn[i - 256];
}

// ---------------------------------------------------------------------------
// prep_a: split hs -> hs_hi/lo ; split hs+pos -> hp_hi/lo (one pass)
// ---------------------------------------------------------------------------
__device__ __forceinline__ void split_store4(float4 v,
    __nv_bfloat16* ph, __nv_bfloat16* pl)
{
    __nv_bfloat16 h0, l0, h1, l1, h2, l2, h3, l3;
    split1(v.x, h0, l0); split1(v.y, h1, l1);
    split1(v.z, h2, l2); split1(v.w, h3, l3);
    ushort4 H = {__bfloat16_as_ushort(h0), __bfloat16_as_ushort(h1),
                 __bfloat16_as_ushort(h2), __bfloat16_as_ushort(h3)};
    ushort4 L = {__bfloat16_as_ushort(l0), __bfloat16_as_ushort(l1),
                 __bfloat16_as_ushort(l2), __bfloat16_as_ushort(l3)};
    *(ushort4*)ph = H;
    *(ushort4*)pl = L;
}

__global__ __launch_bounds__(256) void prep_a(
    const float* __restrict__ hs, const float* __restrict__ pos)
{
    const int i  = blockIdx.x * 256 + threadIdx.x;   // float4 index
    const int PQ = NQv * 64;
    float4 a = ((const float4*)hs)[i];
    float4 p = ((const float4*)pos)[i % PQ];
    split_store4(a, g_hs_hi + 4 * (size_t)i, g_hs_lo + 4 * (size_t)i);
    a.x += p.x; a.y += p.y; a.z += p.z; a.w += p.w;
    split_store4(a, g_hp_hi + 4 * (size_t)i, g_hp_lo + 4 * (size_t)i);
}

// ---------------------------------------------------------------------------
// bf16x3 GEMM: C[M,Ncols] = (Ah+Al)[M,256] @ (Bh+Bl)^T[Ncols,256] + bias
// HALF_OUT: write C as __half (for values), else float.
// Block 128x64, BK=16, 128 threads (4 warps), warp tile 64x32.
// __launch_bounds__(128,4): 128 regs, 4 blocks/SM = 16 warps/SM.
// ---------------------------------------------------------------------------
#define BM 128
#define BN 64
#define WST 20
#define STAGES 3

__device__ __forceinline__ void mma_bf16(float d[4],
    uint32_t a0, uint32_t a1, uint32_t a2, uint32_t a3,
    uint32_t b0, uint32_t b1)
{
    asm volatile(
        "mma.sync.aligned.m16n8k16.row.col.f32.bf16.bf16.f32 "
        "{%0,%1,%2,%3}, {%4,%5,%6,%7}, {%8,%9}, {%0,%1,%2,%3};\n"
        : "+f"(d[0]), "+f"(d[1]), "+f"(d[2]), "+f"(d[3])
        : "r"(a0), "r"(a1), "r"(a2), "r"(a3), "r"(b0), "r"(b1));
}
__device__ __forceinline__ void ldmx4(uint32_t r[4], uint32_t addr) {
    asm volatile(
        "ldmatrix.sync.aligned.m8n8.x4.shared.b16 {%0,%1,%2,%3}, [%4];\n"
        : "=r"(r[0]), "=r"(r[1]), "=r"(r[2]), "=r"(r[3]) : "r"(addr));
}
__device__ __forceinline__ void cp_async16(uint32_t saddr, const void* g) {
    asm volatile("cp.async.cg.shared.global [%0], [%1], 16;\n"
                 :: "r"(saddr), "l"(g));
}
__device__ __forceinline__ void cp_commit() {
    asm volatile("cp.async.commit_group;\n");
}
template <int N>
__device__ __forceinline__ void cp_wait() {
    asm volatile("cp.async.wait_group %0;\n" :: "n"(N));
}

template <bool HALF_OUT>
__global__ __launch_bounds__(128, 4) void gemm_bf16x3(
    const __nv_bfloat16* __restrict__ Ah, const __nv_bfloat16* __restrict__ Al,
    const __nv_bfloat16* __restrict__ Bh, const __nv_bfloat16* __restrict__ Bl,
    const float* __restrict__ bias, void* __restrict__ Cv, int Ncols)
{
    __shared__ uint32_t As[STAGES][BM * WST];
    __shared__ uint32_t Bs[STAGES][BN * WST];

    const int tid    = threadIdx.x;
    const int lane   = tid & 31;
    const int wid    = tid >> 5;
    const int warp_m = (wid & 1) * 64;
    const int warp_n = (wid >> 1) * 32;
    const int g      = lane >> 2;
    const int t4     = lane & 3;

    const int row0 = blockIdx.x * BM;
    const int col0 = blockIdx.y * BN;

    const int rA = tid;
    const __nv_bfloat16* AgH = Ah + (size_t)(row0 + rA) * 256;
    const __nv_bfloat16* AgL = Al + (size_t)(row0 + rA) * 256;
    const int nB  = tid >> 1;
    const int loB = tid & 1;
    const __nv_bfloat16* Bg = (loB ? Bl : Bh) + (size_t)(col0 + nB) * 256;

    uint32_t sA[STAGES], sB[STAGES];
#pragma unroll
    for (int s = 0; s < STAGES; s++) {
        sA[s] = (uint32_t)__cvta_generic_to_shared(&As[s][rA * WST]);
        sB[s] = (uint32_t)__cvta_generic_to_shared(&Bs[s][nB * WST + loB * 8]);
    }

    auto issue = [&](int s, int k0) {
        cp_async16(sA[s] +  0, AgH + k0);
        cp_async16(sA[s] + 16, AgH + k0 + 8);
        cp_async16(sA[s] + 32, AgL + k0);
        cp_async16(sA[s] + 48, AgL + k0 + 8);
        cp_async16(sB[s] +  0, Bg + k0);
        cp_async16(sB[s] + 16, Bg + k0 + 8);
    };

    float acc[4][4][4];
#pragma unroll
    for (int mi = 0; mi < 4; mi++)
#pragma unroll
        for (int ni = 0; ni < 4; ni++)
#pragma unroll
            for (int j = 0; j < 4; j++) acc[mi][ni][j] = 0.f;

    issue(0, 0);   cp_commit();
    issue(1, 16);  cp_commit();

    const int lrow = lane & 15;
    const int lwof = (lane >> 4) * 4;

    for (int i = 0; i < 16; i++) {
        cp_wait<1>();
        __syncthreads();
        const int st = i % STAGES;
        const uint32_t* bs_ = Bs[st];
        const uint32_t a_base = (uint32_t)__cvta_generic_to_shared(&As[st][0]);

        uint32_t afh[4][4], afl[4][4];
#pragma unroll
        for (int mi = 0; mi < 4; mi++) {
            const uint32_t addr =
                a_base + ((warp_m + mi * 16 + lrow) * WST + lwof) * 4;
            ldmx4(afh[mi], addr);
            ldmx4(afl[mi], addr + 32);
        }
        uint32_t bfh[4][2], bfl[4][2];
#pragma unroll
        for (int ni = 0; ni < 4; ni++) {
            const int n = warp_n + ni * 8 + g;
            bfh[ni][0] = bs_[n * WST + t4];
            bfh[ni][1] = bs_[n * WST + t4 + 4];
            bfl[ni][0] = bs_[n * WST + 8 + t4];
            bfl[ni][1] = bs_[n * WST + 12 + t4];
        }

#pragma unroll
        for (int mi = 0; mi < 4; mi++)
#pragma unroll
            for (int ni = 0; ni < 4; ni++)
                mma_bf16(acc[mi][ni], afh[mi][0], afh[mi][1], afh[mi][2], afh[mi][3],
                         bfh[ni][0], bfh[ni][1]);
#pragma unroll
        for (int mi = 0; mi < 4; mi++)
#pragma unroll
            for (int ni = 0; ni < 4; ni++)
                mma_bf16(acc[mi][ni], afh[mi][0], afh[mi][1], afh[mi][2], afh[mi][3],
                         bfl[ni][0], bfl[ni][1]);
#pragma unroll
        for (int mi = 0; mi < 4; mi++)
#pragma unroll
            for (int ni = 0; ni < 4; ni++)
                mma_bf16(acc[mi][ni], afl[mi][0], afl[mi][1], afl[mi][2], afl[mi][3],
                         bfh[ni][0], bfh[ni][1]);

        const int nk = i + 2;
        if (nk < 16) issue(nk % STAGES, nk * 16);
        cp_commit();
    }

    // Epilogue
#pragma unroll
    for (int mi = 0; mi < 4; mi++) {
        const int r = row0 + warp_m + mi * 16 + g;
#pragma unroll
        for (int ni = 0; ni < 4; ni++) {
            const int c = col0 + warp_n + ni * 8 + t4 * 2;
            const float2 bb = *(const float2*)&bias[c];
            const float v00 = acc[mi][ni][0] + bb.x;
            const float v01 = acc[mi][ni][1] + bb.y;
            const float v10 = acc[mi][ni][2] + bb.x;
            const float v11 = acc[mi][ni][3] + bb.y;
            if (HALF_OUT) {
                __half* C = (__half*)Cv;
                *(__half2*)&C[(size_t)r * Ncols + c] =
                    __floats2half2_rn(v00, v01);
                *(__half2*)&C[(size_t)(r + 8) * Ncols + c] =
                    __floats2half2_rn(v10, v11);
            } else {
                float* C = (float*)Cv;
                *(float2*)&C[(size_t)r * Ncols + c]       = make_float2(v00, v01);
                *(float2*)&C[(size_t)(r + 8) * Ncols + c] = make_float2(v10, v11);
            }
        }
    }
}

// ---------------------------------------------------------------------------
// Deformable sampling + per-head softmax + weighted sum.
// Values are fp16 (half the gather bytes). Writes pre-split bf16 output.
// ---------------------------------------------------------------------------
__global__ __launch_bounds__(256) void deform_sample(
    const float* __restrict__ refp)
{
    const int b = blockIdx.x;       // 0 .. M_TOTAL-1
    const int n = b / NQv;
    const int q = b - n * NQv;

    __shared__ float s_off[256];
    __shared__ float s_attn[128];
    __shared__ int   s_idx[8][16][4];
    __shared__ float s_w[8][16][4];

    const int tid = threadIdx.x;
    s_off[tid] = g_cat[(size_t)b * 384 + tid];
    if (tid < 128) s_attn[tid] = g_cat[(size_t)b * 384 + 256 + tid];
    __syncthreads();

    const int m    = tid >> 5;   // head
    const int lane = tid & 31;
    const int k    = lane & 15;  // point id (lanes 16-31 mirror 0-15)

    float logit = s_attn[m * 16 + k];
    float mx = logit;
#pragma unroll
    for (int s = 8; s > 0; s >>= 1)
        mx = fmaxf(mx, __shfl_xor_sync(0xffffffffu, mx, s));
    float e = __expf(logit - mx);
    float ssum = e;
#pragma unroll
    for (int s = 8; s > 0; s >>= 1)
        ssum += __shfl_xor_sync(0xffffffffu, ssum, s);
    const float wk = e / ssum;

    if (lane < 16) {
        const int l = k >> 2;
        const int p = k & 3;
        const float ref0 = refp[q * 2 + 0];
        const float ref1 = refp[q * 2 + 1];

        const int oidx = ((l * 8 + m) * 4 + p) * 2;
        const float gy = ref0 + s_off[oidx + 0];
        const float gx = ref1 + s_off[oidx + 1];

        const int hw = 64 >> l;
        const int st = (16384 - (16384 >> (2 * l))) / 3;  // 0,4096,5120,5376

        const float scale = hw * 0.5f;
        const float x = gx * scale + (scale - 0.5f);
        const float y = gy * scale + (scale - 0.5f);
        const float x0f = floorf(x);
        const float y0f = floorf(y);
        const float wx = x - x0f;
        const float wy = y - y0f;
        const int x0 = (int)x0f;
        const int y0 = (int)y0f;
        const int x1 = x0 + 1;
        const int y1 = y0 + 1;

        const bool vx0 = (x0 >= 0) & (x0 < hw);
        const bool vx1 = (x1 >= 0) & (x1 < hw);
        const bool vy0 = (y0 >= 0) & (y0 < hw);
        const bool vy1 = (y1 >= 0) & (y1 < hw);

        const int xc0 = min(max(x0, 0), hw - 1);
        const int xc1 = min(max(x1, 0), hw - 1);
        const int yc0 = min(max(y0, 0), hw - 1);
        const int yc1 = min(max(y1, 0), hw - 1);

        int4 idx;
        idx.x = (st + yc0 * hw + xc0) * 256;
        idx.y = (st + yc0 * hw + xc1) * 256;
        idx.z = (st + yc1 * hw + xc0) * 256;
        idx.w = (st + yc1 * hw + xc1) * 256;

        float4 w;
        w.x = wk * (1.f - wx) * (1.f - wy) * (float)(vx0 & vy0);
        w.y = wk * wx * (1.f - wy)         * (float)(vx1 & vy0);
        w.z = wk * (1.f - wx) * wy         * (float)(vx0 & vy1);
        w.w = wk * wx * wy                 * (float)(vx1 & vy1);

        *(int4*)  &s_idx[m][k][0] = idx;
        *(float4*)&s_w[m][k][0]   = w;
    }
    __syncwarp();

    const int corner = lane >> 3;
    const int ch4    = lane & 7;
    const __half* __restrict__ vb =
        g_valh + (size_t)n * ((size_t)NQv * 256) + m * 32 + ch4 * 4;

    float4 acc = {0.f, 0.f, 0.f, 0.f};
#pragma unroll
    for (int kk = 0; kk < 16; kk++) {
        const int   id = s_idx[m][kk][corner];
        const float w  = s_w[m][kk][corner];
        const uint2 raw = *(const uint2*)(vb + id);
        const float2 f01 = __half22float2(*reinterpret_cast<const __half2*>(&raw.x));
        const float2 f23 = __half22float2(*reinterpret_cast<const __half2*>(&raw.y));
        acc.x += w * f01.x;
        acc.y += w * f01.y;
        acc.z += w * f23.x;
        acc.w += w * f23.y;
    }

#pragma unroll
    for (int s = 8; s <= 16; s <<= 1) {
        acc.x += __shfl_xor_sync(0xffffffffu, acc.x, s);
        acc.y += __shfl_xor_sync(0xffffffffu, acc.y, s);
        acc.z += __shfl_xor_sync(0xffffffffu, acc.z, s);
        acc.w += __shfl_xor_sync(0xffffffffu, acc.w, s);
    }

    if (lane < 8) {
        const size_t o = (size_t)b * 256 + m * 32 + lane * 4;
        split_store4(acc, g_sp_hi + o, g_sp_lo + o);
    }
}

// ---------------------------------------------------------------------------
extern "C" void kernel_launch(void* const* d_in, const int* in_sizes, int n_in,
                              void* d_out, int out_size)
{
    const float* hs     = (const float*)d_in[0];   // (4, 5440, 256)
    const float* pos    = (const float*)d_in[1];   // (5440, 256)
    const float* refp   = (const float*)d_in[2];   // (5440, 2)
    // d_in[3] = spatial_shapes (fixed, hardcoded)
    const float* W_off  = (const float*)d_in[4];
    const float* b_off  = (const float*)d_in[5];
    const float* W_attn = (const float*)d_in[6];
    const float* b_attn = (const float*)d_in[7];
    const float* W_val  = (const float*)d_in[8];
    const float* b_val  = (const float*)d_in[9];
    const float* W_out  = (const float*)d_in[10];
    const float* b_out  = (const float*)d_in[11];
    float* out = (float*)d_out;

    __nv_bfloat16 *hsh, *hsl, *hph, *hpl, *sph, *spl;
    __nv_bfloat16 *wvh, *wvl, *wch, *wcl, *woh, *wol;
    __half *gvh;
    float *gc, *bc;
    cudaGetSymbolAddress((void**)&hsh, g_hs_hi);
    cudaGetSymbolAddress((void**)&hsl, g_hs_lo);
    cudaGetSymbolAddress((void**)&hph, g_hp_hi);
    cudaGetSymbolAddress((void**)&hpl, g_hp_lo);
    cudaGetSymbolAddress((void**)&sph, g_sp_hi);
    cudaGetSymbolAddress((void**)&spl, g_sp_lo);
    cudaGetSymbolAddress((void**)&wvh, g_Wval_hi);
    cudaGetSymbolAddress((void**)&wvl, g_Wval_lo);
    cudaGetSymbolAddress((void**)&wch, g_Wcat_hi);
    cudaGetSymbolAddress((void**)&wcl, g_Wcat_lo);
    cudaGetSymbolAddress((void**)&woh, g_Wout_hi);
    cudaGetSymbolAddress((void**)&wol, g_Wout_lo);
    cudaGetSymbolAddress((void**)&gvh, g_valh);
    cudaGetSymbolAddress((void**)&gc, g_cat);
    cudaGetSymbolAddress((void**)&bc, g_bcat);

    // prep
    prep_w<<<896, 256>>>(W_val, W_off, W_attn, W_out, b_off, b_attn);
    prep_a<<<M_TOTAL * 64 / 256, 256>>>(hs, pos);

    dim3 gridV(M_TOTAL / BM, 256 / BN);   // (170, 4)
    dim3 gridC(M_TOTAL / BM, 384 / BN);   // (170, 6)

    // values = hs @ W_val + b_val  (fp16 out)
    gemm_bf16x3<true><<<gridV, 128>>>(hsh, hsl, wvh, wvl, b_val, gvh, 256);
    // [off|attn] = hpos @ Wcat + bcat
    gemm_bf16x3<false><<<gridC, 128>>>(hph, hpl, wch, wcl, bc, gc, 384);
    // sampling + softmax + weighted sum -> g_sp (pre-split bf16)
    deform_sample<<<M_TOTAL, 256>>>(refp);
    // out = sampled @ W_out + b_out
    gemm_bf16x3<false><<<gridV, 128>>>(sph, spl, woh, wol, b_out, out, 256);
}

// round 14
// speedup vs baseline: 2.5003x; 1.0934x over previous
#include <cuda_runtime.h>
#include <cuda_bf16.h>
#include <cuda_fp16.h>
#include <cstddef>
#include <cstdint>

#define NQv    5440
#define NBATCH 4
#define M_TOTAL (NBATCH * NQv)   // 21760

// ---------------- scratch (__device__ globals, allocation-free rule) --------
__device__ __half        g_hsh [(size_t)M_TOTAL * 256];   // hs fp16 hi
__device__ __half        g_hsl [(size_t)M_TOTAL * 256];   // hs fp16 lo
__device__ __nv_bfloat16 g_hph [(size_t)M_TOTAL * 256];   // hs+pos bf16 hi
__device__ __nv_bfloat16 g_hpl [(size_t)M_TOTAL * 256];   // hs+pos bf16 lo
__device__ __half        g_sph [(size_t)M_TOTAL * 256];   // sampled fp16 hi
__device__ __half        g_spl [(size_t)M_TOTAL * 256];   // sampled fp16 lo
__device__ __half        g_Wvalh[256 * 256];              // Wval^T fp16
__device__ __half        g_Wouth[256 * 256];              // Wout^T fp16
__device__ __nv_bfloat16 g_Wcat_hi[384 * 256], g_Wcat_lo[384 * 256];
__device__ float  g_bcat  [384];
__device__ __half g_valh  [(size_t)M_TOTAL * 256];
__device__ float  g_cat   [(size_t)M_TOTAL * 384];   // [off 256 | attn 128]

__device__ __forceinline__ void split1b(float x, __nv_bfloat16& h, __nv_bfloat16& l) {
    h = __float2bfloat16(x);
    l = __float2bfloat16(x - __bfloat162float(h));
}
__device__ __forceinline__ void split1h(float x, __half& h, __half& l) {
    h = __float2half_rn(x);
    l = __float2half_rn(x - __half2float(h));
}

// ---------------------------------------------------------------------------
// prep_w: transpose + convert weights. Wval/Wout -> single fp16.
//         Wcat (off|attn) -> bf16 hi/lo 3-term. bcat built.
// ---------------------------------------------------------------------------
__global__ __launch_bounds__(256) void prep_w(
    const float* __restrict__ Wval, const float* __restrict__ Woff,
    const float* __restrict__ Wattn, const float* __restrict__ Wout,
    const float* __restrict__ boff, const float* __restrict__ battn)
{
    const int i = blockIdx.x * 256 + threadIdx.x;
    if (i < 65536) {                      // Wval: Wt[n][k] = W[k][n]
        const int n = i >> 8, k = i & 255;
        g_Wvalh[n * 256 + k] = __float2half_rn(Wval[k * 256 + n]);
    } else if (i < 65536 + 98304) {       // Wcat: n<256 from Woff, else Wattn
        const int j = i - 65536;
        const int n = j >> 8, k = j & 255;
        const float v = (n < 256) ? Woff[k * 256 + n] : Wattn[k * 128 + (n - 256)];
        __nv_bfloat16 h, l;
        split1b(v, h, l);
        g_Wcat_hi[n * 256 + k] = h;
        g_Wcat_lo[n * 256 + k] = l;
    } else if (i < 229376) {              // Wout
        const int j = i - 163840;
        const int n = j >> 8, k = j & 255;
        g_Wouth[n * 256 + k] = __float2half_rn(Wout[k * 256 + n]);
    }
    if (i < 384) g_bcat[i] = (i < 256) ? boff[i] : battn[i - 256];
}

// ---------------------------------------------------------------------------
// prep_a: hs -> fp16 hi/lo ; hs+pos -> bf16 hi/lo (one pass)
// ---------------------------------------------------------------------------
__device__ __forceinline__ void split_store4b(float4 v,
    __nv_bfloat16* ph, __nv_bfloat16* pl)
{
    __nv_bfloat16 h0, l0, h1, l1, h2, l2, h3, l3;
    split1b(v.x, h0, l0); split1b(v.y, h1, l1);
    split1b(v.z, h2, l2); split1b(v.w, h3, l3);
    ushort4 H = {__bfloat16_as_ushort(h0), __bfloat16_as_ushort(h1),
                 __bfloat16_as_ushort(h2), __bfloat16_as_ushort(h3)};
    ushort4 L = {__bfloat16_as_ushort(l0), __bfloat16_as_ushort(l1),
                 __bfloat16_as_ushort(l2), __bfloat16_as_ushort(l3)};
    *(ushort4*)ph = H;
    *(ushort4*)pl = L;
}
__device__ __forceinline__ void split_store4h(float4 v, __half* ph, __half* pl)
{
    __half h0, l0, h1, l1, h2, l2, h3, l3;
    split1h(v.x, h0, l0); split1h(v.y, h1, l1);
    split1h(v.z, h2, l2); split1h(v.w, h3, l3);
    ushort4 H = {__half_as_ushort(h0), __half_as_ushort(h1),
                 __half_as_ushort(h2), __half_as_ushort(h3)};
    ushort4 L = {__half_as_ushort(l0), __half_as_ushort(l1),
                 __half_as_ushort(l2), __half_as_ushort(l3)};
    *(ushort4*)ph = H;
    *(ushort4*)pl = L;
}

__global__ __launch_bounds__(256) void prep_a(
    const float* __restrict__ hs, const float* __restrict__ pos)
{
    const int i  = blockIdx.x * 256 + threadIdx.x;   // float4 index
    const int PQ = NQv * 64;
    float4 a = ((const float4*)hs)[i];
    float4 p = ((const float4*)pos)[i % PQ];
    split_store4h(a, g_hsh + 4 * (size_t)i, g_hsl + 4 * (size_t)i);
    a.x += p.x; a.y += p.y; a.z += p.z; a.w += p.w;
    split_store4b(a, g_hph + 4 * (size_t)i, g_hpl + 4 * (size_t)i);
}

// ---------------------------------------------------------------------------
// mma.sync GEMM, two modes:
//   TWO=false: bf16 3-term  (A hi/lo bf16, B hi/lo bf16): hh + hl + lh
//   TWO=true : fp16 2-term  (A hi/lo fp16, B single fp16): Ah*B + Al*B
// Block 128x64, BK=16, 128 threads (4 warps), warp tile 64x32, 3-stage
// cp.async ring, ldmatrix.x4 for A frags, early cp.async issue.
// ---------------------------------------------------------------------------
#define BM 128
#define BN 64
#define WSTA 20
#define STAGES 3

template <bool F16>
__device__ __forceinline__ void mma16816(float d[4],
    uint32_t a0, uint32_t a1, uint32_t a2, uint32_t a3,
    uint32_t b0, uint32_t b1)
{
    if (F16)
        asm volatile(
            "mma.sync.aligned.m16n8k16.row.col.f32.f16.f16.f32 "
            "{%0,%1,%2,%3}, {%4,%5,%6,%7}, {%8,%9}, {%0,%1,%2,%3};\n"
            : "+f"(d[0]), "+f"(d[1]), "+f"(d[2]), "+f"(d[3])
            : "r"(a0), "r"(a1), "r"(a2), "r"(a3), "r"(b0), "r"(b1));
    else
        asm volatile(
            "mma.sync.aligned.m16n8k16.row.col.f32.bf16.bf16.f32 "
            "{%0,%1,%2,%3}, {%4,%5,%6,%7}, {%8,%9}, {%0,%1,%2,%3};\n"
            : "+f"(d[0]), "+f"(d[1]), "+f"(d[2]), "+f"(d[3])
            : "r"(a0), "r"(a1), "r"(a2), "r"(a3), "r"(b0), "r"(b1));
}
__device__ __forceinline__ void ldmx4(uint32_t r[4], uint32_t addr) {
    asm volatile(
        "ldmatrix.sync.aligned.m8n8.x4.shared.b16 {%0,%1,%2,%3}, [%4];\n"
        : "=r"(r[0]), "=r"(r[1]), "=r"(r[2]), "=r"(r[3]) : "r"(addr));
}
__device__ __forceinline__ void cp_async16(uint32_t saddr, const void* g) {
    asm volatile("cp.async.cg.shared.global [%0], [%1], 16;\n"
                 :: "r"(saddr), "l"(g));
}
__device__ __forceinline__ void cp_commit() {
    asm volatile("cp.async.commit_group;\n");
}
template <int N>
__device__ __forceinline__ void cp_wait() {
    asm volatile("cp.async.wait_group %0;\n" :: "n"(N));
}

template <bool TWO, bool HALF_OUT>
__global__ __launch_bounds__(128, 4) void gemm_mma(
    const uint16_t* __restrict__ Ah, const uint16_t* __restrict__ Al,
    const uint16_t* __restrict__ Bh, const uint16_t* __restrict__ Bl,
    const float* __restrict__ bias, void* __restrict__ Cv, int Ncols)
{
    constexpr int WSTB = TWO ? 12 : 20;
    __shared__ uint32_t As[STAGES][BM * WSTA];
    __shared__ uint32_t Bs[STAGES][BN * WSTB];

    const int tid    = threadIdx.x;
    const int lane   = tid & 31;
    const int wid    = tid >> 5;
    const int warp_m = (wid & 1) * 64;
    const int warp_n = (wid >> 1) * 32;
    const int g      = lane >> 2;
    const int t4     = lane & 3;

    const int row0 = blockIdx.x * BM;
    const int col0 = blockIdx.y * BN;

    // A loader: thread -> row tid; hi 2x16B + lo 2x16B
    const int rA = tid;
    const uint16_t* AgH = Ah + (size_t)(row0 + rA) * 256;
    const uint16_t* AgL = Al + (size_t)(row0 + rA) * 256;
    // B loader
    const int nB  = tid >> 1;
    const int hB  = tid & 1;   // TWO: k-half; THREE: hi/lo select
    const uint16_t* Bg;
    if (TWO) Bg = Bh + (size_t)(col0 + nB) * 256;
    else     Bg = (hB ? Bl : Bh) + (size_t)(col0 + nB) * 256;

    uint32_t sA[STAGES], sB[STAGES];
#pragma unroll
    for (int s = 0; s < STAGES; s++) {
        sA[s] = (uint32_t)__cvta_generic_to_shared(&As[s][rA * WSTA]);
        if (TWO) sB[s] = (uint32_t)__cvta_generic_to_shared(&Bs[s][nB * WSTB + hB * 4]);
        else     sB[s] = (uint32_t)__cvta_generic_to_shared(&Bs[s][nB * WSTB + hB * 8]);
    }

    auto issue = [&](int s, int k0) {
        cp_async16(sA[s] +  0, AgH + k0);
        cp_async16(sA[s] + 16, AgH + k0 + 8);
        cp_async16(sA[s] + 32, AgL + k0);
        cp_async16(sA[s] + 48, AgL + k0 + 8);
        if (TWO) {
            cp_async16(sB[s], Bg + k0 + hB * 8);      // 1 x 16B per thread
        } else {
            cp_async16(sB[s],      Bg + k0);
            cp_async16(sB[s] + 16, Bg + k0 + 8);
        }
    };

    float acc[4][4][4];
#pragma unroll
    for (int mi = 0; mi < 4; mi++)
#pragma unroll
        for (int ni = 0; ni < 4; ni++)
#pragma unroll
            for (int j = 0; j < 4; j++) acc[mi][ni][j] = 0.f;

    issue(0, 0);   cp_commit();
    issue(1, 16);  cp_commit();

    const int lrow = lane & 15;
    const int lwof = (lane >> 4) * 4;

    for (int i = 0; i < 16; i++) {
        cp_wait<1>();
        __syncthreads();
        // early issue: stage (i+2)%3 was fully consumed before this barrier
        if (i + 2 < 16) issue((i + 2) % STAGES, (i + 2) * 16);
        cp_commit();

        const int st = i % STAGES;
        const uint32_t* bs_ = Bs[st];
        const uint32_t a_base = (uint32_t)__cvta_generic_to_shared(&As[st][0]);

        uint32_t afh[4][4], afl[4][4];
#pragma unroll
        for (int mi = 0; mi < 4; mi++) {
            const uint32_t addr =
                a_base + ((warp_m + mi * 16 + lrow) * WSTA + lwof) * 4;
            ldmx4(afh[mi], addr);
            ldmx4(afl[mi], addr + 32);
        }
        uint32_t bfh[4][2];
#pragma unroll
        for (int ni = 0; ni < 4; ni++) {
            const int n = warp_n + ni * 8 + g;
            bfh[ni][0] = bs_[n * WSTB + t4];
            bfh[ni][1] = bs_[n * WSTB + t4 + 4];
        }

#pragma unroll
        for (int mi = 0; mi < 4; mi++)
#pragma unroll
            for (int ni = 0; ni < 4; ni++)
                mma16816<TWO>(acc[mi][ni],
                    afh[mi][0], afh[mi][1], afh[mi][2], afh[mi][3],
                    bfh[ni][0], bfh[ni][1]);
#pragma unroll
        for (int mi = 0; mi < 4; mi++)
#pragma unroll
            for (int ni = 0; ni < 4; ni++)
                mma16816<TWO>(acc[mi][ni],
                    afl[mi][0], afl[mi][1], afl[mi][2], afl[mi][3],
                    bfh[ni][0], bfh[ni][1]);

        if (!TWO) {
            uint32_t bfl[4][2];
#pragma unroll
            for (int ni = 0; ni < 4; ni++) {
                const int n = warp_n + ni * 8 + g;
                bfl[ni][0] = bs_[n * WSTB + 8 + t4];
                bfl[ni][1] = bs_[n * WSTB + 12 + t4];
            }
#pragma unroll
            for (int mi = 0; mi < 4; mi++)
#pragma unroll
                for (int ni = 0; ni < 4; ni++)
                    mma16816<TWO>(acc[mi][ni],
                        afh[mi][0], afh[mi][1], afh[mi][2], afh[mi][3],
                        bfl[ni][0], bfl[ni][1]);
        }
    }

    // Epilogue: bias + store; (c0,c1) at row, (c2,c3) at row+8
#pragma unroll
    for (int mi = 0; mi < 4; mi++) {
        const int r = row0 + warp_m + mi * 16 + g;
#pragma unroll
        for (int ni = 0; ni < 4; ni++) {
            const int c = col0 + warp_n + ni * 8 + t4 * 2;
            const float2 bb = *(const float2*)&bias[c];
            const float v00 = acc[mi][ni][0] + bb.x;
            const float v01 = acc[mi][ni][1] + bb.y;
            const float v10 = acc[mi][ni][2] + bb.x;
            const float v11 = acc[mi][ni][3] + bb.y;
            if (HALF_OUT) {
                __half* C = (__half*)Cv;
                *(__half2*)&C[(size_t)r * Ncols + c] =
                    __floats2half2_rn(v00, v01);
                *(__half2*)&C[(size_t)(r + 8) * Ncols + c] =
                    __floats2half2_rn(v10, v11);
            } else {
                float* C = (float*)Cv;
                *(float2*)&C[(size_t)r * Ncols + c]       = make_float2(v00, v01);
                *(float2*)&C[(size_t)(r + 8) * Ncols + c] = make_float2(v10, v11);
            }
        }
    }
}

// ---------------------------------------------------------------------------
// Deformable sampling + per-head softmax + weighted sum.
// Values fp16; output pre-split fp16 hi/lo for the 2-term out GEMM.
// ---------------------------------------------------------------------------
__global__ __launch_bounds__(256) void deform_sample(
    const float* __restrict__ refp)
{
    const int b = blockIdx.x;       // 0 .. M_TOTAL-1
    const int n = b / NQv;
    const int q = b - n * NQv;

    __shared__ float s_off[256];
    __shared__ float s_attn[128];
    __shared__ int   s_idx[8][16][4];
    __shared__ float s_w[8][16][4];

    const int tid = threadIdx.x;
    s_off[tid] = g_cat[(size_t)b * 384 + tid];
    if (tid < 128) s_attn[tid] = g_cat[(size_t)b * 384 + 256 + tid];
    __syncthreads();

    const int m    = tid >> 5;   // head
    const int lane = tid & 31;
    const int k    = lane & 15;  // point id (lanes 16-31 mirror 0-15)

    float logit = s_attn[m * 16 + k];
    float mx = logit;
#pragma unroll
    for (int s = 8; s > 0; s >>= 1)
        mx = fmaxf(mx, __shfl_xor_sync(0xffffffffu, mx, s));
    float e = __expf(logit - mx);
    float ssum = e;
#pragma unroll
    for (int s = 8; s > 0; s >>= 1)
        ssum += __shfl_xor_sync(0xffffffffu, ssum, s);
    const float wk = e / ssum;

    if (lane < 16) {
        const int l = k >> 2;
        const int p = k & 3;
        const float ref0 = refp[q * 2 + 0];
        const float ref1 = refp[q * 2 + 1];

        const int oidx = ((l * 8 + m) * 4 + p) * 2;
        const float gy = ref0 + s_off[oidx + 0];
        const float gx = ref1 + s_off[oidx + 1];

        const int hw = 64 >> l;
        const int st = (16384 - (16384 >> (2 * l))) / 3;  // 0,4096,5120,5376

        const float scale = hw * 0.5f;
        const float x = gx * scale + (scale - 0.5f);
        const float y = gy * scale + (scale - 0.5f);
        const float x0f = floorf(x);
        const float y0f = floorf(y);
        const float wx = x - x0f;
        const float wy = y - y0f;
        const int x0 = (int)x0f;
        const int y0 = (int)y0f;
        const int x1 = x0 + 1;
        const int y1 = y0 + 1;

        const bool vx0 = (x0 >= 0) & (x0 < hw);
        const bool vx1 = (x1 >= 0) & (x1 < hw);
        const bool vy0 = (y0 >= 0) & (y0 < hw);
        const bool vy1 = (y1 >= 0) & (y1 < hw);

        const int xc0 = min(max(x0, 0), hw - 1);
        const int xc1 = min(max(x1, 0), hw - 1);
        const int yc0 = min(max(y0, 0), hw - 1);
        const int yc1 = min(max(y1, 0), hw - 1);

        int4 idx;
        idx.x = (st + yc0 * hw + xc0) * 256;
        idx.y = (st + yc0 * hw + xc1) * 256;
        idx.z = (st + yc1 * hw + xc0) * 256;
        idx.w = (st + yc1 * hw + xc1) * 256;

        float4 w;
        w.x = wk * (1.f - wx) * (1.f - wy) * (float)(vx0 & vy0);
        w.y = wk * wx * (1.f - wy)         * (float)(vx1 & vy0);
        w.z = wk * (1.f - wx) * wy         * (float)(vx0 & vy1);
        w.w = wk * wx * wy                 * (float)(vx1 & vy1);

        *(int4*)  &s_idx[m][k][0] = idx;
        *(float4*)&s_w[m][k][0]   = w;
    }
    __syncwarp();

    const int corner = lane >> 3;
    const int ch4    = lane & 7;
    const __half* __restrict__ vb =
        g_valh + (size_t)n * ((size_t)NQv * 256) + m * 32 + ch4 * 4;

    float4 acc = {0.f, 0.f, 0.f, 0.f};
#pragma unroll
    for (int kk = 0; kk < 16; kk++) {
        const int   id = s_idx[m][kk][corner];
        const float w  = s_w[m][kk][corner];
        const uint2 raw = *(const uint2*)(vb + id);
        const float2 f01 = __half22float2(*reinterpret_cast<const __half2*>(&raw.x));
        const float2 f23 = __half22float2(*reinterpret_cast<const __half2*>(&raw.y));
        acc.x += w * f01.x;
        acc.y += w * f01.y;
        acc.z += w * f23.x;
        acc.w += w * f23.y;
    }

#pragma unroll
    for (int s = 8; s <= 16; s <<= 1) {
        acc.x += __shfl_xor_sync(0xffffffffu, acc.x, s);
        acc.y += __shfl_xor_sync(0xffffffffu, acc.y, s);
        acc.z += __shfl_xor_sync(0xffffffffu, acc.z, s);
        acc.w += __shfl_xor_sync(0xffffffffu, acc.w, s);
    }

    if (lane < 8) {
        const size_t o = (size_t)b * 256 + m * 32 + lane * 4;
        split_store4h(acc, g_sph + o, g_spl + o);
    }
}

// ---------------------------------------------------------------------------
extern "C" void kernel_launch(void* const* d_in, const int* in_sizes, int n_in,
                              void* d_out, int out_size)
{
    const float* hs     = (const float*)d_in[0];   // (4, 5440, 256)
    const float* pos    = (const float*)d_in[1];   // (5440, 256)
    const float* refp   = (const float*)d_in[2];   // (5440, 2)
    // d_in[3] = spatial_shapes (fixed, hardcoded)
    const float* W_off  = (const float*)d_in[4];
    const float* b_off  = (const float*)d_in[5];
    const float* W_attn = (const float*)d_in[6];
    const float* b_attn = (const float*)d_in[7];
    const float* W_val  = (const float*)d_in[8];
    const float* b_val  = (const float*)d_in[9];
    const float* W_out  = (const float*)d_in[10];
    const float* b_out  = (const float*)d_in[11];
    float* out = (float*)d_out;

    void *hsh, *hsl, *hph, *hpl, *sph, *spl, *wv, *wo, *wch, *wcl;
    void *gvh, *gc, *bc;
    cudaGetSymbolAddress(&hsh, g_hsh);
    cudaGetSymbolAddress(&hsl, g_hsl);
    cudaGetSymbolAddress(&hph, g_hph);
    cudaGetSymbolAddress(&hpl, g_hpl);
    cudaGetSymbolAddress(&sph, g_sph);
    cudaGetSymbolAddress(&spl, g_spl);
    cudaGetSymbolAddress(&wv,  g_Wvalh);
    cudaGetSymbolAddress(&wo,  g_Wouth);
    cudaGetSymbolAddress(&wch, g_Wcat_hi);
    cudaGetSymbolAddress(&wcl, g_Wcat_lo);
    cudaGetSymbolAddress(&gvh, g_valh);
    cudaGetSymbolAddress(&gc,  g_cat);
    cudaGetSymbolAddress(&bc,  g_bcat);

    // prep
    prep_w<<<896, 256>>>(W_val, W_off, W_attn, W_out, b_off, b_attn);
    prep_a<<<M_TOTAL * 64 / 256, 256>>>(hs, pos);

    dim3 gridV(M_TOTAL / BM, 256 / BN);   // (170, 4)
    dim3 gridC(M_TOTAL / BM, 384 / BN);   // (170, 6)

    // values = hs @ W_val + b_val   (fp16 2-term, fp16 out)
    gemm_mma<true, true><<<gridV, 128>>>(
        (const uint16_t*)hsh, (const uint16_t*)hsl,
        (const uint16_t*)wv, (const uint16_t*)nullptr, b_val, gvh, 256);
    // [off|attn] = hpos @ Wcat + bcat   (bf16 3-term, f32 out)
    gemm_mma<false, false><<<gridC, 128>>>(
        (const uint16_t*)hph, (const uint16_t*)hpl,
        (const uint16_t*)wch, (const uint16_t*)wcl,
        (const float*)bc, gc, 384);
    // sampling + softmax + weighted sum -> g_sp (pre-split fp16)
    deform_sample<<<M_TOTAL, 256>>>(refp);
    // out = sampled @ W_out + b_out   (fp16 2-term, f32 out)
    gemm_mma<true, false><<<gridV, 128>>>(
        (const uint16_t*)sph, (const uint16_t*)spl,
        (const uint16_t*)wo, (const uint16_t*)nullptr, b_out, out, 256);
}

// round 15
// speedup vs baseline: 2.8922x; 1.1567x over previous
#include <cuda_runtime.h>
#include <cuda_bf16.h>
#include <cuda_fp16.h>
#include <cstddef>
#include <cstdint>

#define NQv    5440
#define NBATCH 4
#define M_TOTAL (NBATCH * NQv)   // 21760

// ---------------- scratch (__device__ globals, allocation-free rule) --------
__device__ __half        g_hsh [(size_t)M_TOTAL * 256];   // hs fp16 (single)
__device__ __nv_bfloat16 g_hph [(size_t)M_TOTAL * 256];   // hs+pos bf16 hi
__device__ __nv_bfloat16 g_hpl [(size_t)M_TOTAL * 256];   // hs+pos bf16 lo
__device__ __half        g_sph [(size_t)M_TOTAL * 256];   // sampled fp16 (single)
__device__ __half        g_Wvalh[256 * 256];              // Wval^T fp16
__device__ __half        g_Wouth[256 * 256];              // Wout^T fp16
__device__ __nv_bfloat16 g_Wcat_hi[384 * 256], g_Wcat_lo[384 * 256];
__device__ float  g_bcat  [384];
// values, HEAD-MAJOR: [n][head][pix(NQv)][dh(32)] fp16
__device__ __half g_valh  [(size_t)M_TOTAL * 256];
__device__ float  g_cat   [(size_t)M_TOTAL * 384];   // [off 256 | attn 128]

__device__ __forceinline__ void split1b(float x, __nv_bfloat16& h, __nv_bfloat16& l) {
    h = __float2bfloat16(x);
    l = __float2bfloat16(x - __bfloat162float(h));
}

// ---------------------------------------------------------------------------
// prep_w: transpose + convert weights. Wval/Wout -> single fp16.
//         Wcat (off|attn) -> bf16 hi/lo 3-term. bcat built.
// ---------------------------------------------------------------------------
__global__ __launch_bounds__(256) void prep_w(
    const float* __restrict__ Wval, const float* __restrict__ Woff,
    const float* __restrict__ Wattn, const float* __restrict__ Wout,
    const float* __restrict__ boff, const float* __restrict__ battn)
{
    const int i = blockIdx.x * 256 + threadIdx.x;
    if (i < 65536) {                      // Wval: Wt[n][k] = W[k][n]
        const int n = i >> 8, k = i & 255;
        g_Wvalh[n * 256 + k] = __float2half_rn(Wval[k * 256 + n]);
    } else if (i < 65536 + 98304) {       // Wcat: n<256 from Woff, else Wattn
        const int j = i - 65536;
        const int n = j >> 8, k = j & 255;
        const float v = (n < 256) ? Woff[k * 256 + n] : Wattn[k * 128 + (n - 256)];
        __nv_bfloat16 h, l;
        split1b(v, h, l);
        g_Wcat_hi[n * 256 + k] = h;
        g_Wcat_lo[n * 256 + k] = l;
    } else if (i < 229376) {              // Wout
        const int j = i - 163840;
        const int n = j >> 8, k = j & 255;
        g_Wouth[n * 256 + k] = __float2half_rn(Wout[k * 256 + n]);
    }
    if (i < 384) g_bcat[i] = (i < 256) ? boff[i] : battn[i - 256];
}

// ---------------------------------------------------------------------------
// prep_a: hs -> fp16 (single) ; hs+pos -> bf16 hi/lo (one pass)
// ---------------------------------------------------------------------------
__device__ __forceinline__ void split_store4b(float4 v,
    __nv_bfloat16* ph, __nv_bfloat16* pl)
{
    __nv_bfloat16 h0, l0, h1, l1, h2, l2, h3, l3;
    split1b(v.x, h0, l0); split1b(v.y, h1, l1);
    split1b(v.z, h2, l2); split1b(v.w, h3, l3);
    ushort4 H = {__bfloat16_as_ushort(h0), __bfloat16_as_ushort(h1),
                 __bfloat16_as_ushort(h2), __bfloat16_as_ushort(h3)};
    ushort4 L = {__bfloat16_as_ushort(l0), __bfloat16_as_ushort(l1),
                 __bfloat16_as_ushort(l2), __bfloat16_as_ushort(l3)};
    *(ushort4*)ph = H;
    *(ushort4*)pl = L;
}
__device__ __forceinline__ void store4h(float4 v, __half* ph)
{
    ushort4 H = {__half_as_ushort(__float2half_rn(v.x)),
                 __half_as_ushort(__float2half_rn(v.y)),
                 __half_as_ushort(__float2half_rn(v.z)),
                 __half_as_ushort(__float2half_rn(v.w))};
    *(ushort4*)ph = H;
}

__global__ __launch_bounds__(256) void prep_a(
    const float* __restrict__ hs, const float* __restrict__ pos)
{
    const int i  = blockIdx.x * 256 + threadIdx.x;   // float4 index
    const int PQ = NQv * 64;
    float4 a = ((const float4*)hs)[i];
    float4 p = ((const float4*)pos)[i % PQ];
    store4h(a, g_hsh + 4 * (size_t)i);
    a.x += p.x; a.y += p.y; a.z += p.z; a.w += p.w;
    split_store4b(a, g_hph + 4 * (size_t)i, g_hpl + 4 * (size_t)i);
}

// ---------------------------------------------------------------------------
// mma.sync GEMM, three modes:
//   MODE 0 (cat):    bf16 3-term (A hi/lo, B hi/lo), f32 out row-major
//   MODE 1 (values): fp16 1-term (A single, B single), fp16 out HEAD-MAJOR
//   MODE 2 (out):    fp16 1-term (A single, B single), f32 out row-major
// Block 128x64, BK=16, 128 threads (4 warps), warp tile 64x32, 3-stage
// cp.async ring, ldmatrix.x4 for A frags, early cp.async issue.
// ---------------------------------------------------------------------------
#define BM 128
#define BN 64
#define STAGES 3

template <bool F16>
__device__ __forceinline__ void mma16816(float d[4],
    uint32_t a0, uint32_t a1, uint32_t a2, uint32_t a3,
    uint32_t b0, uint32_t b1)
{
    if (F16)
        asm volatile(
            "mma.sync.aligned.m16n8k16.row.col.f32.f16.f16.f32 "
            "{%0,%1,%2,%3}, {%4,%5,%6,%7}, {%8,%9}, {%0,%1,%2,%3};\n"
            : "+f"(d[0]), "+f"(d[1]), "+f"(d[2]), "+f"(d[3])
            : "r"(a0), "r"(a1), "r"(a2), "r"(a3), "r"(b0), "r"(b1));
    else
        asm volatile(
            "mma.sync.aligned.m16n8k16.row.col.f32.bf16.bf16.f32 "
            "{%0,%1,%2,%3}, {%4,%5,%6,%7}, {%8,%9}, {%0,%1,%2,%3};\n"
            : "+f"(d[0]), "+f"(d[1]), "+f"(d[2]), "+f"(d[3])
            : "r"(a0), "r"(a1), "r"(a2), "r"(a3), "r"(b0), "r"(b1));
}
__device__ __forceinline__ void ldmx4(uint32_t r[4], uint32_t addr) {
    asm volatile(
        "ldmatrix.sync.aligned.m8n8.x4.shared.b16 {%0,%1,%2,%3}, [%4];\n"
        : "=r"(r[0]), "=r"(r[1]), "=r"(r[2]), "=r"(r[3]) : "r"(addr));
}
__device__ __forceinline__ void cp_async16(uint32_t saddr, const void* g) {
    asm volatile("cp.async.cg.shared.global [%0], [%1], 16;\n"
                 :: "r"(saddr), "l"(g));
}
__device__ __forceinline__ void cp_commit() {
    asm volatile("cp.async.commit_group;\n");
}
template <int N>
__device__ __forceinline__ void cp_wait() {
    asm volatile("cp.async.wait_group %0;\n" :: "n"(N));
}

template <int MODE>
__global__ __launch_bounds__(128, 4) void gemm_mma(
    const uint16_t* __restrict__ Ah, const uint16_t* __restrict__ Al,
    const uint16_t* __restrict__ Bh, const uint16_t* __restrict__ Bl,
    const float* __restrict__ bias, void* __restrict__ Cv, int Ncols)
{
    constexpr bool THREE = (MODE == 0);
    constexpr int WSTA = THREE ? 20 : 12;
    constexpr int WSTB = THREE ? 20 : 12;
    __shared__ uint32_t As[STAGES][BM * WSTA];
    __shared__ uint32_t Bs[STAGES][BN * WSTB];

    const int tid    = threadIdx.x;
    const int lane   = tid & 31;
    const int wid    = tid >> 5;
    const int warp_m = (wid & 1) * 64;
    const int warp_n = (wid >> 1) * 32;
    const int g      = lane >> 2;
    const int t4     = lane & 3;

    const int row0 = blockIdx.x * BM;
    const int col0 = blockIdx.y * BN;

    // A loader: thread -> row tid
    const int rA = tid;
    const uint16_t* AgH = Ah + (size_t)(row0 + rA) * 256;
    const uint16_t* AgL = THREE ? (Al + (size_t)(row0 + rA) * 256) : nullptr;
    // B loader
    const int nB  = tid >> 1;
    const int hB  = tid & 1;   // THREE: hi/lo select; 1-term: k-half
    const uint16_t* Bg;
    if (THREE) Bg = (hB ? Bl : Bh) + (size_t)(col0 + nB) * 256;
    else       Bg = Bh + (size_t)(col0 + nB) * 256;

    uint32_t sA[STAGES], sB[STAGES];
#pragma unroll
    for (int s = 0; s < STAGES; s++) {
        sA[s] = (uint32_t)__cvta_generic_to_shared(&As[s][rA * WSTA]);
        if (THREE) sB[s] = (uint32_t)__cvta_generic_to_shared(&Bs[s][nB * WSTB + hB * 8]);
        else       sB[s] = (uint32_t)__cvta_generic_to_shared(&Bs[s][nB * WSTB + hB * 4]);
    }

    auto issue = [&](int s, int k0) {
        cp_async16(sA[s] +  0, AgH + k0);
        cp_async16(sA[s] + 16, AgH + k0 + 8);
        if (THREE) {
            cp_async16(sA[s] + 32, AgL + k0);
            cp_async16(sA[s] + 48, AgL + k0 + 8);
            cp_async16(sB[s],      Bg + k0);
            cp_async16(sB[s] + 16, Bg + k0 + 8);
        } else {
            cp_async16(sB[s], Bg + k0 + hB * 8);
        }
    };

    float acc[4][4][4];
#pragma unroll
    for (int mi = 0; mi < 4; mi++)
#pragma unroll
        for (int ni = 0; ni < 4; ni++)
#pragma unroll
            for (int j = 0; j < 4; j++) acc[mi][ni][j] = 0.f;

    issue(0, 0);   cp_commit();
    issue(1, 16);  cp_commit();

    const int lrow = lane & 15;
    const int lwof = (lane >> 4) * 4;

    for (int i = 0; i < 16; i++) {
        cp_wait<1>();
        __syncthreads();
        // early issue: stage (i+2)%3 was fully consumed before this barrier
        if (i + 2 < 16) issue((i + 2) % STAGES, (i + 2) * 16);
        cp_commit();

        const int st = i % STAGES;
        const uint32_t* bs_ = Bs[st];
        const uint32_t a_base = (uint32_t)__cvta_generic_to_shared(&As[st][0]);

        uint32_t afh[4][4];
#pragma unroll
        for (int mi = 0; mi < 4; mi++) {
            const uint32_t addr =
                a_base + ((warp_m + mi * 16 + lrow) * WSTA + lwof) * 4;
            ldmx4(afh[mi], addr);
        }
        uint32_t bfh[4][2];
#pragma unroll
        for (int ni = 0; ni < 4; ni++) {
            const int n = warp_n + ni * 8 + g;
            bfh[ni][0] = bs_[n * WSTB + t4];
            bfh[ni][1] = bs_[n * WSTB + t4 + 4];
        }

#pragma unroll
        for (int mi = 0; mi < 4; mi++)
#pragma unroll
            for (int ni = 0; ni < 4; ni++)
                mma16816<!THREE>(acc[mi][ni],
                    afh[mi][0], afh[mi][1], afh[mi][2], afh[mi][3],
                    bfh[ni][0], bfh[ni][1]);

        if (THREE) {
            uint32_t afl[4][4];
#pragma unroll
            for (int mi = 0; mi < 4; mi++) {
                const uint32_t addr =
                    a_base + ((warp_m + mi * 16 + lrow) * WSTA + lwof) * 4;
                ldmx4(afl[mi], addr + 32);
            }
            uint32_t bfl[4][2];
#pragma unroll
            for (int ni = 0; ni < 4; ni++) {
                const int n = warp_n + ni * 8 + g;
                bfl[ni][0] = bs_[n * WSTB + 8 + t4];
                bfl[ni][1] = bs_[n * WSTB + 12 + t4];
            }
#pragma unroll
            for (int mi = 0; mi < 4; mi++)
#pragma unroll
                for (int ni = 0; ni < 4; ni++)
                    mma16816<false>(acc[mi][ni],
                        afh[mi][0], afh[mi][1], afh[mi][2], afh[mi][3],
                        bfl[ni][0], bfl[ni][1]);
#pragma unroll
            for (int mi = 0; mi < 4; mi++)
#pragma unroll
                for (int ni = 0; ni < 4; ni++)
                    mma16816<false>(acc[mi][ni],
                        afl[mi][0], afl[mi][1], afl[mi][2], afl[mi][3],
                        bfh[ni][0], bfh[ni][1]);
        }
    }

    // Epilogue
#pragma unroll
    for (int mi = 0; mi < 4; mi++) {
        const int r = row0 + warp_m + mi * 16 + g;
#pragma unroll
        for (int ni = 0; ni < 4; ni++) {
            const int c = col0 + warp_n + ni * 8 + t4 * 2;
            const float2 bb = *(const float2*)&bias[c];
            const float v00 = acc[mi][ni][0] + bb.x;
            const float v01 = acc[mi][ni][1] + bb.y;
            const float v10 = acc[mi][ni][2] + bb.x;
            const float v11 = acc[mi][ni][3] + bb.y;
            if (MODE == 1) {
                // head-major fp16 scatter: [n][head][pix][dh]
                __half* C = (__half*)Cv;
                const int head = c >> 5, dh = c & 31;
                {
                    const int n0 = r / NQv, q0 = r - n0 * NQv;
                    __half2* p = (__half2*)&C[(((size_t)(n0 * 8 + head)) * NQv + q0) * 32 + dh];
                    *p = __floats2half2_rn(v00, v01);
                }
                {
                    const int r1 = r + 8;
                    const int n1 = r1 / NQv, q1 = r1 - n1 * NQv;
                    __half2* p = (__half2*)&C[(((size_t)(n1 * 8 + head)) * NQv + q1) * 32 + dh];
                    *p = __floats2half2_rn(v10, v11);
                }
            } else {
                float* C = (float*)Cv;
                *(float2*)&C[(size_t)r * Ncols + c]       = make_float2(v00, v01);
                *(float2*)&C[(size_t)(r + 8) * Ncols + c] = make_float2(v10, v11);
            }
        }
    }
}

// ---------------------------------------------------------------------------
// Deformable sampling + per-head softmax + weighted sum.
// Values fp16 HEAD-MAJOR [n][head][pix][32]: x-adjacent corners contiguous.
// Output: single fp16 (for the 1-term out GEMM).
// ---------------------------------------------------------------------------
__global__ __launch_bounds__(256) void deform_sample(
    const float* __restrict__ refp)
{
    const int b = blockIdx.x;       // 0 .. M_TOTAL-1
    const int n = b / NQv;
    const int q = b - n * NQv;

    __shared__ float s_off[256];
    __shared__ float s_attn[128];
    __shared__ int   s_idx[8][16][4];
    __shared__ float s_w[8][16][4];

    const int tid = threadIdx.x;
    s_off[tid] = g_cat[(size_t)b * 384 + tid];
    if (tid < 128) s_attn[tid] = g_cat[(size_t)b * 384 + 256 + tid];
    __syncthreads();

    const int m    = tid >> 5;   // head
    const int lane = tid & 31;
    const int k    = lane & 15;  // point id (lanes 16-31 mirror 0-15)

    float logit = s_attn[m * 16 + k];
    float mx = logit;
#pragma unroll
    for (int s = 8; s > 0; s >>= 1)
        mx = fmaxf(mx, __shfl_xor_sync(0xffffffffu, mx, s));
    float e = __expf(logit - mx);
    float ssum = e;
#pragma unroll
    for (int s = 8; s > 0; s >>= 1)
        ssum += __shfl_xor_sync(0xffffffffu, ssum, s);
    const float wk = e / ssum;

    if (lane < 16) {
        const int l = k >> 2;
        const int p = k & 3;
        const float ref0 = refp[q * 2 + 0];
        const float ref1 = refp[q * 2 + 1];

        const int oidx = ((l * 8 + m) * 4 + p) * 2;
        const float gy = ref0 + s_off[oidx + 0];
        const float gx = ref1 + s_off[oidx + 1];

        const int hw = 64 >> l;
        const int st = (16384 - (16384 >> (2 * l))) / 3;  // 0,4096,5120,5376

        const float scale = hw * 0.5f;
        const float x = gx * scale + (scale - 0.5f);
        const float y = gy * scale + (scale - 0.5f);
        const float x0f = floorf(x);
        const float y0f = floorf(y);
        const float wx = x - x0f;
        const float wy = y - y0f;
        const int x0 = (int)x0f;
        const int y0 = (int)y0f;
        const int x1 = x0 + 1;
        const int y1 = y0 + 1;

        const bool vx0 = (x0 >= 0) & (x0 < hw);
        const bool vx1 = (x1 >= 0) & (x1 < hw);
        const bool vy0 = (y0 >= 0) & (y0 < hw);
        const bool vy1 = (y1 >= 0) & (y1 < hw);

        const int xc0 = min(max(x0, 0), hw - 1);
        const int xc1 = min(max(x1, 0), hw - 1);
        const int yc0 = min(max(y0, 0), hw - 1);
        const int yc1 = min(max(y1, 0), hw - 1);

        // pixel index * 32 (head-major: pixel stride = 32 halves)
        int4 idx;
        idx.x = (st + yc0 * hw + xc0) * 32;
        idx.y = (st + yc0 * hw + xc1) * 32;
        idx.z = (st + yc1 * hw + xc0) * 32;
        idx.w = (st + yc1 * hw + xc1) * 32;

        float4 w;
        w.x = wk * (1.f - wx) * (1.f - wy) * (float)(vx0 & vy0);
        w.y = wk * wx * (1.f - wy)         * (float)(vx1 & vy0);
        w.z = wk * (1.f - wx) * wy         * (float)(vx0 & vy1);
        w.w = wk * wx * wy                 * (float)(vx1 & vy1);

        *(int4*)  &s_idx[m][k][0] = idx;
        *(float4*)&s_w[m][k][0]   = w;
    }
    __syncwarp();

    const int corner = lane >> 3;
    const int ch4    = lane & 7;
    const __half* __restrict__ vb =
        g_valh + ((size_t)(n * 8 + m)) * ((size_t)NQv * 32) + ch4 * 4;

    float4 acc = {0.f, 0.f, 0.f, 0.f};
#pragma unroll
    for (int kk = 0; kk < 16; kk++) {
        const int   id = s_idx[m][kk][corner];
        const float w  = s_w[m][kk][corner];
        const uint2 raw = *(const uint2*)(vb + id);
        const float2 f01 = __half22float2(*reinterpret_cast<const __half2*>(&raw.x));
        const float2 f23 = __half22float2(*reinterpret_cast<const __half2*>(&raw.y));
        acc.x += w * f01.x;
        acc.y += w * f01.y;
        acc.z += w * f23.x;
        acc.w += w * f23.y;
    }

#pragma unroll
    for (int s = 8; s <= 16; s <<= 1) {
        acc.x += __shfl_xor_sync(0xffffffffu, acc.x, s);
        acc.y += __shfl_xor_sync(0xffffffffu, acc.y, s);
        acc.z += __shfl_xor_sync(0xffffffffu, acc.z, s);
        acc.w += __shfl_xor_sync(0xffffffffu, acc.w, s);
    }

    if (lane < 8) {
        const size_t o = (size_t)b * 256 + m * 32 + lane * 4;
        store4h(acc, g_sph + o);
    }
}

// ---------------------------------------------------------------------------
extern "C" void kernel_launch(void* const* d_in, const int* in_sizes, int n_in,
                              void* d_out, int out_size)
{
    const float* hs     = (const float*)d_in[0];   // (4, 5440, 256)
    const float* pos    = (const float*)d_in[1];   // (5440, 256)
    const float* refp   = (const float*)d_in[2];   // (5440, 2)
    // d_in[3] = spatial_shapes (fixed, hardcoded)
    const float* W_off  = (const float*)d_in[4];
    const float* b_off  = (const float*)d_in[5];
    const float* W_attn = (const float*)d_in[6];
    const float* b_attn = (const float*)d_in[7];
    const float* W_val  = (const float*)d_in[8];
    const float* b_val  = (const float*)d_in[9];
    const float* W_out  = (const float*)d_in[10];
    const float* b_out  = (const float*)d_in[11];
    float* out = (float*)d_out;

    void *hsh, *hph, *hpl, *sph, *wv, *wo, *wch, *wcl, *gvh, *gc, *bc;
    cudaGetSymbolAddress(&hsh, g_hsh);
    cudaGetSymbolAddress(&hph, g_hph);
    cudaGetSymbolAddress(&hpl, g_hpl);
    cudaGetSymbolAddress(&sph, g_sph);
    cudaGetSymbolAddress(&wv,  g_Wvalh);
    cudaGetSymbolAddress(&wo,  g_Wouth);
    cudaGetSymbolAddress(&wch, g_Wcat_hi);
    cudaGetSymbolAddress(&wcl, g_Wcat_lo);
    cudaGetSymbolAddress(&gvh, g_valh);
    cudaGetSymbolAddress(&gc,  g_cat);
    cudaGetSymbolAddress(&bc,  g_bcat);

    // prep
    prep_w<<<896, 256>>>(W_val, W_off, W_attn, W_out, b_off, b_attn);
    prep_a<<<M_TOTAL * 64 / 256, 256>>>(hs, pos);

    dim3 gridV(M_TOTAL / BM, 256 / BN);   // (170, 4)
    dim3 gridC(M_TOTAL / BM, 384 / BN);   // (170, 6)

    // values = hs @ W_val + b_val   (fp16 1-term, fp16 head-major out)
    gemm_mma<1><<<gridV, 128>>>(
        (const uint16_t*)hsh, (const uint16_t*)nullptr,
        (const uint16_t*)wv, (const uint16_t*)nullptr, b_val, gvh, 256);
    // [off|attn] = hpos @ Wcat + bcat   (bf16 3-term, f32 out)
    gemm_mma<0><<<gridC, 128>>>(
        (const uint16_t*)hph, (const uint16_t*)hpl,
        (const uint16_t*)wch, (const uint16_t*)wcl,
        (const float*)bc, gc, 384);
    // sampling + softmax + weighted sum -> g_sph (fp16)
    deform_sample<<<M_TOTAL, 256>>>(refp);
    // out = sampled @ W_out + b_out   (fp16 1-term, f32 out)
    gemm_mma<2><<<gridV, 128>>>(
        (const uint16_t*)sph, (const uint16_t*)nullptr,
        (const uint16_t*)wo, (const uint16_t*)nullptr, b_out, out, 256);
}